// round 2
// baseline (speedup 1.0000x reference)
#include <cuda_runtime.h>
#include <mma.h>
#include <cstdint>
#include <cstddef>

using namespace nvcuda;

#define Tt 10
#define Bb 16
#define Ss 200
#define Dd 768
#define Hh 300
#define K5 3840            // 5*D
#define NPAD 2432          // 1216 (fwd block) + 1216 (bwd block)
#define NDIRBASE 1216
#define Mm 32000           // T*S*B
#define LDK 320            // padded recurrent K (300 -> 320)

// ---------------- device scratch (allocation-free) ----------------
__device__ float g_X[(size_t)Mm * K5];       // 491.5 MB
__device__ float g_W[(size_t)NPAD * K5];     // 37.3 MB
__device__ float g_C[(size_t)Mm * NPAD];     // 311.3 MB
__device__ float g_ws[Tt * Bb * Ss];
__device__ float g_we[Tt * Bb * Ss];
__device__ float g_wbs[Bb * Ss];
__device__ float g_wbe[Bb * Ss];
__device__ float g_y[(size_t)Tt * Ss * Bb * 600];  // 76.8 MB, [t][s][b][2H]
__device__ float g_h[2 * 2 * Bb * LDK];      // [dir][parity][b][LDK]
__device__ unsigned g_cnt;

// ---------------- kernel 1: fused attention weights ----------------
__global__ void k_weights(const float* __restrict__ sp, const float* __restrict__ ep,
                          const float* __restrict__ cp,
                          const float* __restrict__ bsp, const float* __restrict__ bep,
                          const float* __restrict__ bcp,
                          const float* __restrict__ um, const float* __restrict__ nm,
                          const float* __restrict__ am) {
    int idx = blockIdx.x * blockDim.x + threadIdx.x;
    if (idx >= Tt * Bb * Ss) return;
    int t = idx / (Bb * Ss);
    int r = idx % (Bb * Ss);
    int b = r / Ss;
    int s = r % Ss;
    // masks are [B,T,S]
    float amv = am[(b * Tt + t) * Ss + s];
    float umv = um[(b * Tt + t) * Ss + s];
    float nmv = nm[(b * Tt + t) * Ss + s];
    const float* c = cp + (t * Bb + b) * 4;
    float wb = amv * c[0] + umv * c[1] + nmv * c[2];
    g_ws[idx] = sp[idx] * wb;
    g_we[idx] = ep[idx] * wb;
    if (t == 0) {
        const float* bc = bcp + b * 4;  // before_state_classification_probs[0]
        float wbb = amv * bc[0] + umv * bc[1] + nmv * bc[2];
        g_wbs[b * Ss + s] = bsp[b * Ss + s] * wbb;
        g_wbe[b * Ss + s] = bep[b * Ss + s] * wbb;
    }
}

// ---------------- kernel 2: stacked + gate-permuted + tf32-rounded Wih -------
// new row r (within a 1216 block): tile=r/16, gate=(r%16)/4, cc=r%4
// source row = gate*300 + tile*4 + cc  (rows >=1200 are zero padding)
__global__ void k_wpad(const float* __restrict__ wf, const float* __restrict__ wb) {
    int rrow = blockIdx.x;
    int dir = rrow >= NDIRBASE;
    int rp = dir ? rrow - NDIRBASE : rrow;
    const float* src = nullptr;
    if (rp < 1200) {
        int tile = rp >> 4, gate = (rp >> 2) & 3, cc = rp & 3;
        int srow = gate * 300 + tile * 4 + cc;
        src = (dir ? wb : wf) + (size_t)srow * K5;
    }
    float* dst = g_W + (size_t)rrow * K5;
    for (int c = threadIdx.x * 4; c < K5; c += blockDim.x * 4) {
        float4 v = make_float4(0.f, 0.f, 0.f, 0.f);
        if (src) {
            v = *(const float4*)(src + c);
            v.x = wmma::__float_to_tf32(v.x);
            v.y = wmma::__float_to_tf32(v.y);
            v.z = wmma::__float_to_tf32(v.z);
            v.w = wmma::__float_to_tf32(v.w);
        }
        *(float4*)(dst + c) = v;
    }
}

// ---------------- kernel 3: build X = [seq | ws*seq | we*seq | wps*seqp | wpe*seqp]
__global__ void k_xbuild(const float* __restrict__ seq) {
    int m = blockIdx.x;          // ((t*200+s)*16+b)
    int b = m & 15;
    int ts = m >> 4;
    int s = ts % Ss;
    int t = ts / Ss;
    int tp = (t > 0) ? (t - 1) : 0;
    int c = threadIdx.x * 4;     // 192 threads -> 768 cols
    const float4 sv = *(const float4*)(seq + (((size_t)(t * Bb + b) * Ss + s) * Dd) + c);
    const float4 pv = *(const float4*)(seq + (((size_t)(tp * Bb + b) * Ss + s) * Dd) + c);
    int widx = (t * Bb + b) * Ss + s;
    float w1 = g_ws[widx], w2 = g_we[widx];
    float wp1, wp2;
    if (t > 0) {
        int pidx = ((t - 1) * Bb + b) * Ss + s;
        wp1 = g_ws[pidx];
        wp2 = g_we[pidx];
    } else {
        wp1 = g_wbs[b * Ss + s];
        wp2 = g_wbe[b * Ss + s];
    }
    float* X = g_X + (size_t)m * K5 + c;
#define R4(dst, a, wgt) do { \
        float4 _v; \
        _v.x = wmma::__float_to_tf32((a).x * (wgt)); \
        _v.y = wmma::__float_to_tf32((a).y * (wgt)); \
        _v.z = wmma::__float_to_tf32((a).z * (wgt)); \
        _v.w = wmma::__float_to_tf32((a).w * (wgt)); \
        *(float4*)(dst) = _v; } while (0)
    R4(X,            sv, 1.f);
    R4(X + 768,      sv, w1);
    R4(X + 1536,     sv, w2);
    R4(X + 2304,     pv, wp1);
    R4(X + 3072,     pv, wp2);
#undef R4
}

// ---------------- kernel 4: tf32 wmma GEMM  C[M,NPAD] = X[M,K5] * W[NPAD,K5]^T
#define GLD 40
__global__ void __launch_bounds__(256) k_gemm() {
    __shared__ float As[128 * GLD];
    __shared__ float Bs[128 * GLD];
    int mt = blockIdx.y, nt = blockIdx.x;
    int tid = threadIdx.x;
    int wid = tid >> 5;
    int wy = wid >> 1, wx = wid & 1;     // 4x2 warp grid; warp tile 32x64
    int lr = tid >> 1, lh = tid & 1;     // loader: row, half

    wmma::fragment<wmma::accumulator, 16, 16, 8, float> acc[2][4];
#pragma unroll
    for (int i = 0; i < 2; ++i)
#pragma unroll
        for (int j = 0; j < 4; ++j) wmma::fill_fragment(acc[i][j], 0.f);

    const float* AG = g_X + (size_t)(mt * 128 + lr) * K5 + lh * 16;
    const float* BG = g_W + (size_t)(nt * 128 + lr) * K5 + lh * 16;
    float* Asw = As + lr * GLD + lh * 16;
    float* Bsw = Bs + lr * GLD + lh * 16;

    for (int kt = 0; kt < K5 / 32; ++kt) {
#pragma unroll
        for (int i = 0; i < 4; ++i) {
            *(float4*)(Asw + i * 4) = *(const float4*)(AG + kt * 32 + i * 4);
            *(float4*)(Bsw + i * 4) = *(const float4*)(BG + kt * 32 + i * 4);
        }
        __syncthreads();
#pragma unroll
        for (int ks = 0; ks < 4; ++ks) {
            wmma::fragment<wmma::matrix_a, 16, 16, 8, wmma::precision::tf32, wmma::row_major> a0, a1;
            wmma::load_matrix_sync(a0, As + (wy * 32) * GLD + ks * 8, GLD);
            wmma::load_matrix_sync(a1, As + (wy * 32 + 16) * GLD + ks * 8, GLD);
#pragma unroll
            for (int j = 0; j < 4; ++j) {
                wmma::fragment<wmma::matrix_b, 16, 16, 8, wmma::precision::tf32, wmma::col_major> bf;
                wmma::load_matrix_sync(bf, Bs + (wx * 64 + j * 16) * GLD + ks * 8, GLD);
                wmma::mma_sync(acc[0][j], a0, bf, acc[0][j]);
                wmma::mma_sync(acc[1][j], a1, bf, acc[1][j]);
            }
        }
        __syncthreads();
    }
#pragma unroll
    for (int i = 0; i < 2; ++i)
#pragma unroll
        for (int j = 0; j < 4; ++j) {
            float* cp = g_C + (size_t)(mt * 128 + wy * 32 + i * 16) * NPAD
                        + nt * 128 + wx * 64 + j * 16;
            wmma::store_matrix_sync(cp, acc[i][j], NPAD, wmma::mem_row_major);
        }
}

// ---------------- kernel 5: persistent bidirectional LSTM scan ----------------
__device__ __forceinline__ float sigm(float x) {
    return 1.f / (1.f + __expf(-x));
}
__device__ __forceinline__ float tanh_fast(float x) {
    x = fminf(fmaxf(x, -15.f), 15.f);
    float e = __expf(-2.f * x);
    return (1.f - e) / (1.f + e);
}

extern __shared__ float sm_lstm[];
__global__ void __launch_bounds__(256, 1) k_lstm(
        const float* __restrict__ whf, const float* __restrict__ whb,
        const float* __restrict__ bihf, const float* __restrict__ bhhf,
        const float* __restrict__ bihb, const float* __restrict__ bhhb) {
    float* WhhS = sm_lstm;                  // [2][16][LDK]
    float* hS   = WhhS + 2 * 16 * LDK;      // [2][16][LDK]
    float* accS = hS + 2 * 16 * LDK;        // [8][256]
    float* cS   = accS + 8 * 256;           // [2][64]
    float* bS   = cS + 128;                 // [2][16]

    int tid = threadIdx.x;
    int tile = blockIdx.x;                  // 0..74, owns h-cols [4*tile, 4*tile+4)

    // prologue: Whh slices (gate-permuted, tf32-rounded) resident in shared
    for (int e = tid; e < 2 * 16 * LDK; e += 256) {
        int k = e % LDK;
        int lrr = (e / LDK) & 15;
        int dir = e / (16 * LDK);
        int gate = lrr >> 2, cc = lrr & 3;
        int srow = gate * 300 + tile * 4 + cc;
        float v = 0.f;
        if (k < 300) v = wmma::__float_to_tf32((dir ? whb : whf)[srow * 300 + k]);
        WhhS[e] = v;
    }
    if (tid < 32) {
        int dir = tid >> 4, lrr = tid & 15;
        int gate = lrr >> 2, cc = lrr & 3;
        int srow = gate * 300 + tile * 4 + cc;
        bS[tid] = dir ? (bihb[srow] + bhhb[srow]) : (bihf[srow] + bhhf[srow]);
    }
    if (tid < 128) cS[tid] = 0.f;
    __syncthreads();

    int wid = tid >> 5;
    int dirw = wid >> 2, kq = wid & 3;       // warps 0-3 fwd, 4-7 bwd; k-split x4
    int edir = tid >> 6, eidx = tid & 63, ecc = eidx >> 4, eb = eidx & 15;

    for (int g = 0; g < Tt * Ss; ++g) {
        int t = g / Ss, s = g % Ss;
        int parity = g & 1;

        // prefetch z from big-GEMM output (no cross-CTA dependency)
        float z0 = 0.f, z1 = 0.f, z2 = 0.f, z3 = 0.f;
        int pos = 0;
        if (tid < 128) {
            pos = edir ? (Ss - 1 - s) : s;
            size_t m = (size_t)(t * Ss + pos) * Bb + eb;
            const float* crow = g_C + m * NPAD + (edir ? NDIRBASE : 0) + tile * 16;
            z0 = crow[0 + ecc];
            z1 = crow[4 + ecc];
            z2 = crow[8 + ecc];
            z3 = crow[12 + ecc];
        }

        // stage both directions' h into shared
        {
            const float4* hg = (const float4*)g_h;
            float4* hs4 = (float4*)hS;
            const int Q = LDK / 4;  // 80
            for (int i = tid; i < 2 * 16 * Q; i += 256) {
                int dir = i / (16 * Q);
                int rem = i % (16 * Q);
                hs4[dir * 16 * Q + rem] = hg[((dir * 2 + parity) * 16) * Q + rem];
            }
        }
        __syncthreads();

        // recurrent matmul: [16b x 320k] x [320k x 16 gate-rows]
        {
            wmma::fragment<wmma::accumulator, 16, 16, 8, float> acc;
            wmma::fill_fragment(acc, 0.f);
#pragma unroll
            for (int it = 0; it < 10; ++it) {
                int k = kq * 80 + it * 8;
                wmma::fragment<wmma::matrix_a, 16, 16, 8, wmma::precision::tf32, wmma::row_major> af;
                wmma::fragment<wmma::matrix_b, 16, 16, 8, wmma::precision::tf32, wmma::col_major> bf;
                wmma::load_matrix_sync(af, hS + dirw * 16 * LDK + k, LDK);
                wmma::load_matrix_sync(bf, WhhS + dirw * 16 * LDK + k, LDK);
                wmma::mma_sync(acc, af, bf, acc);
            }
            wmma::store_matrix_sync(accS + wid * 256, acc, 16, wmma::mem_row_major);
        }
        __syncthreads();

        // gates + state update for 4 h-cols x 16 batches per direction
        if (tid < 128) {
            float* ab = accS + edir * 4 * 256 + eb * 16;
            float zi = z0 + bS[edir * 16 + 0 + ecc]  + ab[0 + ecc]  + ab[256 + 0 + ecc]  + ab[512 + 0 + ecc]  + ab[768 + 0 + ecc];
            float zf = z1 + bS[edir * 16 + 4 + ecc]  + ab[4 + ecc]  + ab[256 + 4 + ecc]  + ab[512 + 4 + ecc]  + ab[768 + 4 + ecc];
            float zg = z2 + bS[edir * 16 + 8 + ecc]  + ab[8 + ecc]  + ab[256 + 8 + ecc]  + ab[512 + 8 + ecc]  + ab[768 + 8 + ecc];
            float zo = z3 + bS[edir * 16 + 12 + ecc] + ab[12 + ecc] + ab[256 + 12 + ecc] + ab[512 + 12 + ecc] + ab[768 + 12 + ecc];
            float ig = sigm(zi);
            float fg = sigm(zf);
            float gg = tanh_fast(zg);
            float og = sigm(zo);
            float cold = cS[edir * 64 + eidx];
            float cnew = fg * cold + ig * gg;
            float hval = og * tanh_fast(cnew);
            cS[edir * 64 + eidx] = cnew;
            int jh = tile * 4 + ecc;
            g_h[((edir * 2 + (parity ^ 1)) * Bb + eb) * LDK + jh] = wmma::__float_to_tf32(hval);
            g_y[((size_t)(t * Ss + pos) * Bb + eb) * 600 + edir * 300 + jh] = hval;
            __threadfence();
        }
        __syncthreads();

        // software grid barrier across the 75 CTAs
        if (tid == 0) {
            atomicAdd(&g_cnt, 1u);
            unsigned target = 75u * (unsigned)(g + 1);
            while (*((volatile unsigned*)&g_cnt) < target) { }
        }
        __syncthreads();
    }
}

// ---------------- kernel 6: classifier logits = relu(y) @ Wcls^T + bcls -------
__global__ void k_cls(const float* __restrict__ W, const float* __restrict__ bc,
                      float* __restrict__ out) {
    int t = blockIdx.x >> 4, b = blockIdx.x & 15;
    float a0 = 0.f, a1 = 0.f, a2 = 0.f, a3 = 0.f;
    const size_t NW = 120000;
    for (int idx = threadIdx.x; idx < (int)NW; idx += 256) {
        int s = idx / 600, c = idx % 600;
        float yv = g_y[((size_t)(t * Ss + s) * Bb + b) * 600 + c];
        yv = fmaxf(yv, 0.f);
        a0 += yv * W[idx];
        a1 += yv * W[NW + idx];
        a2 += yv * W[2 * NW + idx];
        a3 += yv * W[3 * NW + idx];
    }
#pragma unroll
    for (int off = 16; off; off >>= 1) {
        a0 += __shfl_down_sync(0xFFFFFFFFu, a0, off);
        a1 += __shfl_down_sync(0xFFFFFFFFu, a1, off);
        a2 += __shfl_down_sync(0xFFFFFFFFu, a2, off);
        a3 += __shfl_down_sync(0xFFFFFFFFu, a3, off);
    }
    __shared__ float rs[8][4];
    if ((threadIdx.x & 31) == 0) {
        int w = threadIdx.x >> 5;
        rs[w][0] = a0; rs[w][1] = a1; rs[w][2] = a2; rs[w][3] = a3;
    }
    __syncthreads();
    if (threadIdx.x < 4) {
        float sv = bc[threadIdx.x];
#pragma unroll
        for (int w = 0; w < 8; ++w) sv += rs[w][threadIdx.x];
        out[blockIdx.x * 4 + threadIdx.x] = sv;
    }
}

// ---------------- host launcher ----------------
extern "C" void kernel_launch(void* const* d_in, const int* in_sizes, int n_in,
                              void* d_out, int out_size) {
    const float* seq  = (const float*)d_in[1];
    const float* sp   = (const float*)d_in[2];
    const float* ep   = (const float*)d_in[3];
    const float* cp   = (const float*)d_in[4];
    const float* bsp  = (const float*)d_in[5];
    const float* bep  = (const float*)d_in[6];
    const float* bcp  = (const float*)d_in[7];
    const float* um   = (const float*)d_in[8];
    const float* nm   = (const float*)d_in[9];
    const float* am   = (const float*)d_in[10];
    const float* wihf = (const float*)d_in[11];
    const float* whhf = (const float*)d_in[12];
    const float* bihf = (const float*)d_in[13];
    const float* bhhf = (const float*)d_in[14];
    const float* wihb = (const float*)d_in[15];
    const float* whhb = (const float*)d_in[16];
    const float* bihb = (const float*)d_in[17];
    const float* bhhb = (const float*)d_in[18];
    const float* wcls = (const float*)d_in[19];
    const float* bcls = (const float*)d_in[20];
    float* out = (float*)d_out;

    const int LSTM_SMEM = (2 * 16 * LDK + 2 * 16 * LDK + 8 * 256 + 128 + 32) * 4; // 90752 B
    cudaFuncSetAttribute(k_lstm, cudaFuncAttributeMaxDynamicSharedMemorySize, LSTM_SMEM);

    void* cntp = nullptr;
    void* hp = nullptr;
    cudaGetSymbolAddress(&cntp, g_cnt);
    cudaGetSymbolAddress(&hp, g_h);
    cudaMemsetAsync(cntp, 0, sizeof(unsigned));
    cudaMemsetAsync(hp, 0, sizeof(float) * 2 * 2 * Bb * LDK);

    k_weights<<<(Tt * Bb * Ss + 255) / 256, 256>>>(sp, ep, cp, bsp, bep, bcp, um, nm, am);
    k_wpad<<<NPAD, 256>>>(wihf, wihb);
    k_xbuild<<<Mm, 192>>>(seq);
    dim3 gg(NPAD / 128, Mm / 128);
    k_gemm<<<gg, 256>>>();
    k_lstm<<<75, 256, LSTM_SMEM>>>(whhf, whhb, bihf, bhhf, bihb, bhhb);
    k_cls<<<Tt * Bb, 256>>>(wcls, bcls, out);
}

// round 4
// speedup vs baseline: 1.3880x; 1.3880x over previous
#include <cuda_runtime.h>
#include <cuda_bf16.h>
#include <mma.h>
#include <cstdint>
#include <cstddef>

using namespace nvcuda;

#define Tt 10
#define Bb 16
#define Ss 200
#define Dd 768
#define K5 3840            // 5*D
#define NPAD 2432          // 1216 (fwd block) + 1216 (bwd block)
#define NDIRBASE 1216
#define Mm 32000           // T*S*B
#define LDK 320            // padded recurrent K in GLOBAL h buffer
#define LDH 340            // padded shared stride for LSTM (2-way conflicts only)
#define NCTA_L 75

// ---------------- device scratch (allocation-free) ----------------
__device__ float g_X[(size_t)Mm * K5];       // 491.5 MB
__device__ float g_W[(size_t)NPAD * K5];     // 37.3 MB
__device__ float g_C[(size_t)Mm * NPAD];     // 311.3 MB
__device__ float g_ws[Tt * Bb * Ss];
__device__ float g_we[Tt * Bb * Ss];
__device__ float g_wbs[Bb * Ss];
__device__ float g_wbe[Bb * Ss];
__device__ float g_y[(size_t)Tt * Ss * Bb * 600];  // [t][s][b][2H]
__device__ float g_h[2 * 2 * Bb * LDK];      // [dir][parity][b][LDK]
__device__ unsigned g_cnt;
__device__ unsigned g_flag;

// ---------------- helpers ----------------
__device__ __forceinline__ uint32_t smem_u32(const void* p) {
    uint32_t a;
    asm("{ .reg .u64 t; cvta.to.shared.u64 t, %1; cvt.u32.u64 %0, t; }" : "=r"(a) : "l"(p));
    return a;
}
__device__ __forceinline__ void cp16(uint32_t d, const void* s) {
    asm volatile("cp.async.cg.shared.global [%0], [%1], 16;" :: "r"(d), "l"(s) : "memory");
}

// ---------------- kernel 1: fused attention weights ----------------
__global__ void k_weights(const float* __restrict__ sp, const float* __restrict__ ep,
                          const float* __restrict__ cp,
                          const float* __restrict__ bsp, const float* __restrict__ bep,
                          const float* __restrict__ bcp,
                          const float* __restrict__ um, const float* __restrict__ nm,
                          const float* __restrict__ am) {
    int idx = blockIdx.x * blockDim.x + threadIdx.x;
    if (idx >= Tt * Bb * Ss) return;
    int t = idx / (Bb * Ss);
    int r = idx % (Bb * Ss);
    int b = r / Ss;
    int s = r % Ss;
    // masks are [B,T,S]
    float amv = am[(b * Tt + t) * Ss + s];
    float umv = um[(b * Tt + t) * Ss + s];
    float nmv = nm[(b * Tt + t) * Ss + s];
    const float* c = cp + (t * Bb + b) * 4;
    float wb = amv * c[0] + umv * c[1] + nmv * c[2];
    g_ws[idx] = sp[idx] * wb;
    g_we[idx] = ep[idx] * wb;
    if (t == 0) {
        const float* bc = bcp + b * 4;
        float wbb = amv * bc[0] + umv * bc[1] + nmv * bc[2];
        g_wbs[b * Ss + s] = bsp[b * Ss + s] * wbb;
        g_wbe[b * Ss + s] = bep[b * Ss + s] * wbb;
    }
}

// ---------------- kernel 2: stacked + gate-permuted + tf32-rounded Wih -------
// new row r (within a 1216 block): tile=r/16, gate=(r%16)/4, cc=r%4
// source row = gate*300 + tile*4 + cc  (rows >=1200 are zero padding)
__global__ void k_wpad(const float* __restrict__ wf, const float* __restrict__ wb) {
    int rrow = blockIdx.x;
    int dir = rrow >= NDIRBASE;
    int rp = dir ? rrow - NDIRBASE : rrow;
    const float* src = nullptr;
    if (rp < 1200) {
        int tile = rp >> 4, gate = (rp >> 2) & 3, cc = rp & 3;
        int srow = gate * 300 + tile * 4 + cc;
        src = (dir ? wb : wf) + (size_t)srow * K5;
    }
    float* dst = g_W + (size_t)rrow * K5;
    for (int c = threadIdx.x * 4; c < K5; c += blockDim.x * 4) {
        float4 v = make_float4(0.f, 0.f, 0.f, 0.f);
        if (src) {
            v = *(const float4*)(src + c);
            v.x = wmma::__float_to_tf32(v.x);
            v.y = wmma::__float_to_tf32(v.y);
            v.z = wmma::__float_to_tf32(v.z);
            v.w = wmma::__float_to_tf32(v.w);
        }
        *(float4*)(dst + c) = v;
    }
}

// ---------------- kernel 3: build X = [seq | ws*seq | we*seq | wps*seqp | wpe*seqp]
__global__ void k_xbuild(const float* __restrict__ seq) {
    int m = blockIdx.x;          // ((t*200+s)*16+b)
    int b = m & 15;
    int ts = m >> 4;
    int s = ts % Ss;
    int t = ts / Ss;
    int tp = (t > 0) ? (t - 1) : 0;
    int c = threadIdx.x * 4;     // 192 threads -> 768 cols
    const float4 sv = *(const float4*)(seq + (((size_t)(t * Bb + b) * Ss + s) * Dd) + c);
    const float4 pv = *(const float4*)(seq + (((size_t)(tp * Bb + b) * Ss + s) * Dd) + c);
    int widx = (t * Bb + b) * Ss + s;
    float w1 = g_ws[widx], w2 = g_we[widx];
    float wp1, wp2;
    if (t > 0) {
        int pidx = ((t - 1) * Bb + b) * Ss + s;
        wp1 = g_ws[pidx];
        wp2 = g_we[pidx];
    } else {
        wp1 = g_wbs[b * Ss + s];
        wp2 = g_wbe[b * Ss + s];
    }
    float* X = g_X + (size_t)m * K5 + c;
#define R4(dst, a, wgt) do { \
        float4 _v; \
        _v.x = wmma::__float_to_tf32((a).x * (wgt)); \
        _v.y = wmma::__float_to_tf32((a).y * (wgt)); \
        _v.z = wmma::__float_to_tf32((a).z * (wgt)); \
        _v.w = wmma::__float_to_tf32((a).w * (wgt)); \
        *(float4*)(dst) = _v; } while (0)
    R4(X,            sv, 1.f);
    R4(X + 768,      sv, w1);
    R4(X + 1536,     sv, w2);
    R4(X + 2304,     pv, wp1);
    R4(X + 3072,     pv, wp2);
#undef R4
}

// ---------------- kernel 4: pipelined tf32 wmma GEMM  C = X * W^T ------------
// CTA tile 128x128x32, 3-stage cp.async pipeline, smem stride 36 (2-way only).
#define GP 36
#define STAGEF (2 * 128 * GP)          // floats per stage (A + B)
#define GSMEM (3 * STAGEF * 4)         // 110592 B

__global__ void __launch_bounds__(256, 1) k_gemm2() {
    extern __shared__ float sm[];
    int tid = threadIdx.x;
    int mt = blockIdx.y, nt = blockIdx.x;
    uint32_t sbase = smem_u32(sm);

    int wid = tid >> 5;
    int wy = wid >> 1, wx = wid & 1;   // 4x2 warps; warp tile 32x64

    // loader mapping: 1024 16B-chunks per matrix per stage; 4 per thread
    int lrow0 = tid >> 3;              // rows tid/8, +32 per i
    int lc4 = tid & 7;

    const float* AG = g_X + (size_t)(mt * 128) * K5;
    const float* BG = g_W + (size_t)(nt * 128) * K5;

    wmma::fragment<wmma::accumulator, 16, 16, 8, float> acc[2][4];
#pragma unroll
    for (int i = 0; i < 2; ++i)
#pragma unroll
        for (int j = 0; j < 4; ++j) wmma::fill_fragment(acc[i][j], 0.f);

#define LOADSTAGE(kt, st) do { \
        uint32_t sa = sbase + (st) * STAGEF * 4; \
        uint32_t sbb = sa + 128 * GP * 4; \
        int kof = (kt) * 32 + lc4 * 4; \
        _Pragma("unroll") \
        for (int i = 0; i < 4; ++i) { \
            int row = lrow0 + i * 32; \
            cp16(sa  + (row * GP + lc4 * 4) * 4, AG + (size_t)row * K5 + kof); \
            cp16(sbb + (row * GP + lc4 * 4) * 4, BG + (size_t)row * K5 + kof); \
        } \
        asm volatile("cp.async.commit_group;" ::: "memory"); \
    } while (0)

    LOADSTAGE(0, 0);
    LOADSTAGE(1, 1);
    LOADSTAGE(2, 2);

    for (int kt = 0; kt < K5 / 32; ++kt) {
        int st = kt % 3;
        asm volatile("cp.async.wait_group 2;" ::: "memory");
        __syncthreads();
        const float* As = sm + st * STAGEF;
        const float* Bs = As + 128 * GP;
#pragma unroll
        for (int ks = 0; ks < 4; ++ks) {
            wmma::fragment<wmma::matrix_a, 16, 16, 8, wmma::precision::tf32, wmma::row_major> a0, a1;
            wmma::load_matrix_sync(a0, As + (wy * 32) * GP + ks * 8, GP);
            wmma::load_matrix_sync(a1, As + (wy * 32 + 16) * GP + ks * 8, GP);
#pragma unroll
            for (int j = 0; j < 4; ++j) {
                wmma::fragment<wmma::matrix_b, 16, 16, 8, wmma::precision::tf32, wmma::col_major> bf;
                wmma::load_matrix_sync(bf, Bs + (wx * 64 + j * 16) * GP + ks * 8, GP);
                wmma::mma_sync(acc[0][j], a0, bf, acc[0][j]);
                wmma::mma_sync(acc[1][j], a1, bf, acc[1][j]);
            }
        }
        __syncthreads();
        if (kt + 3 < K5 / 32) {
            LOADSTAGE(kt + 3, st);
        } else {
            asm volatile("cp.async.commit_group;" ::: "memory");
        }
    }
#undef LOADSTAGE

#pragma unroll
    for (int i = 0; i < 2; ++i)
#pragma unroll
        for (int j = 0; j < 4; ++j) {
            float* cp = g_C + (size_t)(mt * 128 + wy * 32 + i * 16) * NPAD
                        + nt * 128 + wx * 64 + j * 16;
            wmma::store_matrix_sync(cp, acc[i][j], NPAD, wmma::mem_row_major);
        }
}

// ---------------- kernel 5: persistent bidirectional LSTM scan ----------------
__device__ __forceinline__ float sigm(float x) {
    return 1.f / (1.f + __expf(-x));
}
__device__ __forceinline__ float tanh_fast(float x) {
    x = fminf(fmaxf(x, -15.f), 15.f);
    float e = __expf(-2.f * x);
    return (1.f - e) / (1.f + e);
}

extern __shared__ float sm_lstm[];
__global__ void __launch_bounds__(256, 1) k_lstm(
        const float* __restrict__ whf, const float* __restrict__ whb,
        const float* __restrict__ bihf, const float* __restrict__ bhhf,
        const float* __restrict__ bihb, const float* __restrict__ bhhb) {
    float* WhhS = sm_lstm;                   // [2][16][LDH]
    float* hS   = WhhS + 2 * 16 * LDH;       // [2][16][LDH]
    float* accS = hS + 2 * 16 * LDH;         // [8][256]
    float* cS   = accS + 8 * 256;            // [2][64]
    float* bS   = cS + 128;                  // [2][16]

    int tid = threadIdx.x;
    int tile = blockIdx.x;                   // owns h-cols [4*tile, 4*tile+4)

    // prologue: Whh slices (gate-permuted, tf32-rounded) resident in shared
    for (int e = tid; e < 2 * 16 * LDH; e += 256) {
        int k = e % LDH;
        int lrr = (e / LDH) & 15;
        int dir = e / (16 * LDH);
        int gate = lrr >> 2, cc = lrr & 3;
        int srow = gate * 300 + tile * 4 + cc;
        float v = 0.f;
        if (k < 300) v = wmma::__float_to_tf32((dir ? whb : whf)[srow * 300 + k]);
        WhhS[e] = v;
    }
    if (tid < 32) {
        int dir = tid >> 4, lrr = tid & 15;
        int gate = lrr >> 2, cc = lrr & 3;
        int srow = gate * 300 + tile * 4 + cc;
        bS[tid] = dir ? (bihb[srow] + bhhb[srow]) : (bihf[srow] + bhhf[srow]);
    }
    if (tid < 128) cS[tid] = 0.f;
    __syncthreads();

    int wid = tid >> 5;
    int dirw = wid >> 2, kq = wid & 3;       // warps 0-3 fwd, 4-7 bwd; k-split x4
    int edir = tid >> 6, eidx = tid & 63, ecc = eidx >> 4, eb = eidx & 15;

    // z double buffer: prefetch step 0
    float z0 = 0.f, z1 = 0.f, z2 = 0.f, z3 = 0.f;   // current
    float n0 = 0.f, n1 = 0.f, n2 = 0.f, n3 = 0.f;   // next
    if (tid < 128) {
        int pos0 = edir ? (Ss - 1) : 0;
        const float* crow = g_C + ((size_t)pos0 * Bb + eb) * NPAD
                            + (edir ? NDIRBASE : 0) + tile * 16;
        n0 = crow[0 + ecc]; n1 = crow[4 + ecc]; n2 = crow[8 + ecc]; n3 = crow[12 + ecc];
    }

    for (int g = 0; g < Tt * Ss; ++g) {
        int t = g / Ss, s = g % Ss;
        int parity = g & 1;
        z0 = n0; z1 = n1; z2 = n2; z3 = n3;

        // stage both directions' h into shared (global row LDK=320 -> shared LDH=340)
        {
            const float4* hg = (const float4*)g_h;
            const int Q = LDK / 4;  // 80
            for (int i = tid; i < 2 * 16 * Q; i += 256) {
                int dr = i / (16 * Q);
                int rem = i % (16 * Q);
                int row = rem / Q, off = rem % Q;
                float4 v = hg[((dr * 2 + parity) * Bb + row) * Q + off];
                *(float4*)(hS + (dr * 16 + row) * LDH + off * 4) = v;
            }
        }
        __syncthreads();

        // prefetch next step's z (hidden behind mma + epilogue + barrier)
        if (tid < 128 && g + 1 < Tt * Ss) {
            int gn = g + 1;
            int tn = gn / Ss, sn = gn % Ss;
            int posn = edir ? (Ss - 1 - sn) : sn;
            const float* crow = g_C + ((size_t)(tn * Ss + posn) * Bb + eb) * NPAD
                                + (edir ? NDIRBASE : 0) + tile * 16;
            n0 = crow[0 + ecc]; n1 = crow[4 + ecc]; n2 = crow[8 + ecc]; n3 = crow[12 + ecc];
        }

        // recurrent matmul: [16b x 320k] x [320k x 16 gate-rows]
        {
            wmma::fragment<wmma::accumulator, 16, 16, 8, float> acc;
            wmma::fill_fragment(acc, 0.f);
#pragma unroll
            for (int itk = 0; itk < 10; ++itk) {
                int k = kq * 80 + itk * 8;
                wmma::fragment<wmma::matrix_a, 16, 16, 8, wmma::precision::tf32, wmma::row_major> af;
                wmma::fragment<wmma::matrix_b, 16, 16, 8, wmma::precision::tf32, wmma::col_major> bf;
                wmma::load_matrix_sync(af, hS + dirw * 16 * LDH + k, LDH);
                wmma::load_matrix_sync(bf, WhhS + dirw * 16 * LDH + k, LDH);
                wmma::mma_sync(acc, af, bf, acc);
            }
            wmma::store_matrix_sync(accS + wid * 256, acc, 16, wmma::mem_row_major);
        }
        __syncthreads();

        // gates + state update for 4 h-cols x 16 batches per direction
        if (tid < 128) {
            int pos = edir ? (Ss - 1 - s) : s;
            float* ab = accS + edir * 4 * 256 + eb * 16;
            float zi = z0 + bS[edir * 16 + 0 + ecc]  + ab[0 + ecc]  + ab[256 + 0 + ecc]  + ab[512 + 0 + ecc]  + ab[768 + 0 + ecc];
            float zf = z1 + bS[edir * 16 + 4 + ecc]  + ab[4 + ecc]  + ab[256 + 4 + ecc]  + ab[512 + 4 + ecc]  + ab[768 + 4 + ecc];
            float zg = z2 + bS[edir * 16 + 8 + ecc]  + ab[8 + ecc]  + ab[256 + 8 + ecc]  + ab[512 + 8 + ecc]  + ab[768 + 8 + ecc];
            float zo = z3 + bS[edir * 16 + 12 + ecc] + ab[12 + ecc] + ab[256 + 12 + ecc] + ab[512 + 12 + ecc] + ab[768 + 12 + ecc];
            float ig = sigm(zi);
            float fg = sigm(zf);
            float gg = tanh_fast(zg);
            float og = sigm(zo);
            float cold = cS[edir * 64 + eidx];
            float cnew = fg * cold + ig * gg;
            float hval = og * tanh_fast(cnew);
            cS[edir * 64 + eidx] = cnew;
            int jh = tile * 4 + ecc;
            g_h[((edir * 2 + (parity ^ 1)) * Bb + eb) * LDK + jh] = wmma::__float_to_tf32(hval);
            g_y[((size_t)(t * Ss + pos) * Bb + eb) * 600 + edir * 300 + jh] = hval;
        }
        __syncthreads();

        // grid barrier: counter arrivals, release-store / acquire-load flag
        if (tid == 0) {
            __threadfence();
            unsigned v = atomicAdd(&g_cnt, 1u);
            unsigned target = (unsigned)NCTA_L * (unsigned)(g + 1);
            if (v + 1u == target) {
                asm volatile("st.global.release.gpu.u32 [%0], %1;"
                             :: "l"(&g_flag), "r"(target) : "memory");
            } else {
                unsigned f;
                do {
                    asm volatile("ld.global.acquire.gpu.u32 %0, [%1];"
                                 : "=r"(f) : "l"(&g_flag) : "memory");
                } while (f < target);
            }
            __threadfence();
        }
        __syncthreads();
    }
}

// ---------------- kernel 6: classifier ----------------
__global__ void k_cls(const float* __restrict__ W, const float* __restrict__ bc,
                      float* __restrict__ out) {
    int t = blockIdx.x >> 4, b = blockIdx.x & 15;
    float a0 = 0.f, a1 = 0.f, a2 = 0.f, a3 = 0.f;
    const size_t NW = 120000;
    for (int idx = threadIdx.x; idx < (int)NW; idx += 256) {
        int s = idx / 600, c = idx % 600;
        float yv = g_y[((size_t)(t * Ss + s) * Bb + b) * 600 + c];
        yv = fmaxf(yv, 0.f);
        a0 += yv * W[idx];
        a1 += yv * W[NW + idx];
        a2 += yv * W[2 * NW + idx];
        a3 += yv * W[3 * NW + idx];
    }
#pragma unroll
    for (int off = 16; off; off >>= 1) {
        a0 += __shfl_down_sync(0xFFFFFFFFu, a0, off);
        a1 += __shfl_down_sync(0xFFFFFFFFu, a1, off);
        a2 += __shfl_down_sync(0xFFFFFFFFu, a2, off);
        a3 += __shfl_down_sync(0xFFFFFFFFu, a3, off);
    }
    __shared__ float rs[8][4];
    if ((threadIdx.x & 31) == 0) {
        int w = threadIdx.x >> 5;
        rs[w][0] = a0; rs[w][1] = a1; rs[w][2] = a2; rs[w][3] = a3;
    }
    __syncthreads();
    if (threadIdx.x < 4) {
        float sv = bc[threadIdx.x];
#pragma unroll
        for (int w = 0; w < 8; ++w) sv += rs[w][threadIdx.x];
        out[blockIdx.x * 4 + threadIdx.x] = sv;
    }
}

// ---------------- host launcher ----------------
extern "C" void kernel_launch(void* const* d_in, const int* in_sizes, int n_in,
                              void* d_out, int out_size) {
    const float* seq  = (const float*)d_in[1];
    const float* sp   = (const float*)d_in[2];
    const float* ep   = (const float*)d_in[3];
    const float* cp   = (const float*)d_in[4];
    const float* bsp  = (const float*)d_in[5];
    const float* bep  = (const float*)d_in[6];
    const float* bcp  = (const float*)d_in[7];
    const float* um   = (const float*)d_in[8];
    const float* nm   = (const float*)d_in[9];
    const float* am   = (const float*)d_in[10];
    const float* wihf = (const float*)d_in[11];
    const float* whhf = (const float*)d_in[12];
    const float* bihf = (const float*)d_in[13];
    const float* bhhf = (const float*)d_in[14];
    const float* wihb = (const float*)d_in[15];
    const float* whhb = (const float*)d_in[16];
    const float* bihb = (const float*)d_in[17];
    const float* bhhb = (const float*)d_in[18];
    const float* wcls = (const float*)d_in[19];
    const float* bcls = (const float*)d_in[20];
    float* out = (float*)d_out;

    const int LSTM_SMEM = (2 * 16 * LDH + 2 * 16 * LDH + 8 * 256 + 128 + 32) * 4;
    cudaFuncSetAttribute(k_lstm, cudaFuncAttributeMaxDynamicSharedMemorySize, LSTM_SMEM);
    cudaFuncSetAttribute(k_gemm2, cudaFuncAttributeMaxDynamicSharedMemorySize, GSMEM);

    void* cntp = nullptr;
    void* flagp = nullptr;
    void* hp = nullptr;
    cudaGetSymbolAddress(&cntp, g_cnt);
    cudaGetSymbolAddress(&flagp, g_flag);
    cudaGetSymbolAddress(&hp, g_h);
    cudaMemsetAsync(cntp, 0, sizeof(unsigned));
    cudaMemsetAsync(flagp, 0, sizeof(unsigned));
    cudaMemsetAsync(hp, 0, sizeof(float) * 2 * 2 * Bb * LDK);

    k_weights<<<(Tt * Bb * Ss + 255) / 256, 256>>>(sp, ep, cp, bsp, bep, bcp, um, nm, am);
    k_wpad<<<NPAD, 256>>>(wihf, wihb);
    k_xbuild<<<Mm, 192>>>(seq);
    dim3 gg(NPAD / 128, Mm / 128);
    k_gemm2<<<gg, 256, GSMEM>>>();
    k_lstm<<<NCTA_L, 256, LSTM_SMEM>>>(whhf, whhb, bihf, bhhf, bihb, bhhb);
    k_cls<<<Tt * Bb, 256>>>(wcls, bcls, out);
}

// round 5
// speedup vs baseline: 1.4220x; 1.0245x over previous
#include <cuda_runtime.h>
#include <cuda_bf16.h>
#include <mma.h>
#include <cstdint>
#include <cstddef>

using namespace nvcuda;

#define Tt 10
#define Bb 16
#define Ss 200
#define Dd 768
#define K5 3840            // 5*D
#define NPAD 2432          // 1216 (fwd block) + 1216 (bwd block)
#define NDIRBASE 1216
#define Mm 32000           // T*S*B
#define LDK 320            // padded recurrent K in GLOBAL h buffer
#define LDH 340            // padded shared stride for LSTM
#define LDA 20             // padded accS stride (was 16: 8-way conflicts)
#define NCTA_L 75

// ---------------- device scratch (allocation-free) ----------------
__device__ float g_X[(size_t)Mm * K5];       // 491.5 MB
__device__ float g_W[(size_t)NPAD * K5];     // 37.3 MB
__device__ float g_C[(size_t)Mm * NPAD];     // 311.3 MB
__device__ float g_ws[Tt * Bb * Ss];
__device__ float g_we[Tt * Bb * Ss];
__device__ float g_wbs[Bb * Ss];
__device__ float g_wbe[Bb * Ss];
__device__ float g_y[(size_t)Tt * Ss * Bb * 600];  // [t][s][b][2H]
__device__ float g_h[2 * 2 * Bb * LDK];      // [dir][parity][b][LDK]
__device__ unsigned g_slots[NCTA_L * 8];     // per-CTA barrier slots, 32B stride

// ---------------- helpers ----------------
__device__ __forceinline__ uint32_t smem_u32(const void* p) {
    uint32_t a;
    asm("{ .reg .u64 t; cvta.to.shared.u64 t, %1; cvt.u32.u64 %0, t; }" : "=r"(a) : "l"(p));
    return a;
}
__device__ __forceinline__ void cp16(uint32_t d, const void* s) {
    asm volatile("cp.async.cg.shared.global [%0], [%1], 16;" :: "r"(d), "l"(s) : "memory");
}

// ---------------- kernel 1: fused attention weights ----------------
__global__ void k_weights(const float* __restrict__ sp, const float* __restrict__ ep,
                          const float* __restrict__ cp,
                          const float* __restrict__ bsp, const float* __restrict__ bep,
                          const float* __restrict__ bcp,
                          const float* __restrict__ um, const float* __restrict__ nm,
                          const float* __restrict__ am) {
    int idx = blockIdx.x * blockDim.x + threadIdx.x;
    if (idx >= Tt * Bb * Ss) return;
    int t = idx / (Bb * Ss);
    int r = idx % (Bb * Ss);
    int b = r / Ss;
    int s = r % Ss;
    // masks are [B,T,S]
    float amv = am[(b * Tt + t) * Ss + s];
    float umv = um[(b * Tt + t) * Ss + s];
    float nmv = nm[(b * Tt + t) * Ss + s];
    const float* c = cp + (t * Bb + b) * 4;
    float wb = amv * c[0] + umv * c[1] + nmv * c[2];
    g_ws[idx] = sp[idx] * wb;
    g_we[idx] = ep[idx] * wb;
    if (t == 0) {
        const float* bc = bcp + b * 4;
        float wbb = amv * bc[0] + umv * bc[1] + nmv * bc[2];
        g_wbs[b * Ss + s] = bsp[b * Ss + s] * wbb;
        g_wbe[b * Ss + s] = bep[b * Ss + s] * wbb;
    }
}

// ---------------- kernel 2: stacked + gate-permuted + tf32-rounded Wih -------
__global__ void k_wpad(const float* __restrict__ wf, const float* __restrict__ wb) {
    int rrow = blockIdx.x;
    int dir = rrow >= NDIRBASE;
    int rp = dir ? rrow - NDIRBASE : rrow;
    const float* src = nullptr;
    if (rp < 1200) {
        int tile = rp >> 4, gate = (rp >> 2) & 3, cc = rp & 3;
        int srow = gate * 300 + tile * 4 + cc;
        src = (dir ? wb : wf) + (size_t)srow * K5;
    }
    float* dst = g_W + (size_t)rrow * K5;
    for (int c = threadIdx.x * 4; c < K5; c += blockDim.x * 4) {
        float4 v = make_float4(0.f, 0.f, 0.f, 0.f);
        if (src) {
            v = *(const float4*)(src + c);
            v.x = wmma::__float_to_tf32(v.x);
            v.y = wmma::__float_to_tf32(v.y);
            v.z = wmma::__float_to_tf32(v.z);
            v.w = wmma::__float_to_tf32(v.w);
        }
        *(float4*)(dst + c) = v;
    }
}

// ---------------- kernel 3: build X ----------------
__global__ void k_xbuild(const float* __restrict__ seq) {
    int m = blockIdx.x;          // ((t*200+s)*16+b)
    int b = m & 15;
    int ts = m >> 4;
    int s = ts % Ss;
    int t = ts / Ss;
    int tp = (t > 0) ? (t - 1) : 0;
    int c = threadIdx.x * 4;     // 192 threads -> 768 cols
    const float4 sv = *(const float4*)(seq + (((size_t)(t * Bb + b) * Ss + s) * Dd) + c);
    const float4 pv = *(const float4*)(seq + (((size_t)(tp * Bb + b) * Ss + s) * Dd) + c);
    int widx = (t * Bb + b) * Ss + s;
    float w1 = g_ws[widx], w2 = g_we[widx];
    float wp1, wp2;
    if (t > 0) {
        int pidx = ((t - 1) * Bb + b) * Ss + s;
        wp1 = g_ws[pidx];
        wp2 = g_we[pidx];
    } else {
        wp1 = g_wbs[b * Ss + s];
        wp2 = g_wbe[b * Ss + s];
    }
    float* X = g_X + (size_t)m * K5 + c;
#define R4(dst, a, wgt) do { \
        float4 _v; \
        _v.x = wmma::__float_to_tf32((a).x * (wgt)); \
        _v.y = wmma::__float_to_tf32((a).y * (wgt)); \
        _v.z = wmma::__float_to_tf32((a).z * (wgt)); \
        _v.w = wmma::__float_to_tf32((a).w * (wgt)); \
        *(float4*)(dst) = _v; } while (0)
    R4(X,            sv, 1.f);
    R4(X + 768,      sv, w1);
    R4(X + 1536,     sv, w2);
    R4(X + 2304,     pv, wp1);
    R4(X + 3072,     pv, wp2);
#undef R4
}

// ---------------- kernel 4: pipelined tf32 wmma GEMM, 1 sync per k-tile ------
#define GP 36
#define STAGEF (2 * 128 * GP)          // floats per stage (A + B)
#define GSMEM (3 * STAGEF * 4)         // 110592 B
#define NK (K5 / 32)                   // 120 k-tiles

__global__ void __launch_bounds__(256, 1) k_gemm2() {
    extern __shared__ float sm[];
    int tid = threadIdx.x;
    int mt = blockIdx.y, nt = blockIdx.x;
    uint32_t sbase = smem_u32(sm);

    int wid = tid >> 5;
    int wy = wid >> 1, wx = wid & 1;   // 4x2 warps; warp tile 32x64

    int lrow0 = tid >> 3;              // loader rows tid/8, +32 per i
    int lc4 = tid & 7;

    const float* AG = g_X + (size_t)(mt * 128) * K5;
    const float* BG = g_W + (size_t)(nt * 128) * K5;

    wmma::fragment<wmma::accumulator, 16, 16, 8, float> acc[2][4];
#pragma unroll
    for (int i = 0; i < 2; ++i)
#pragma unroll
        for (int j = 0; j < 4; ++j) wmma::fill_fragment(acc[i][j], 0.f);

#define LOADSTAGE(kt, st) do { \
        uint32_t sa = sbase + (st) * STAGEF * 4; \
        uint32_t sbb = sa + 128 * GP * 4; \
        int kof = (kt) * 32 + lc4 * 4; \
        _Pragma("unroll") \
        for (int i = 0; i < 4; ++i) { \
            int row = lrow0 + i * 32; \
            cp16(sa  + (row * GP + lc4 * 4) * 4, AG + (size_t)row * K5 + kof); \
            cp16(sbb + (row * GP + lc4 * 4) * 4, BG + (size_t)row * K5 + kof); \
        } \
        asm volatile("cp.async.commit_group;" ::: "memory"); \
    } while (0)

    LOADSTAGE(0, 0);
    LOADSTAGE(1, 1);

    for (int kt = 0; kt < NK; ++kt) {
        int st = kt % 3;
        asm volatile("cp.async.wait_group 1;" ::: "memory");
        __syncthreads();
        // issue next loads first: stage (kt+2)%3 == (kt-1)%3, fully consumed
        // by every thread before the sync above => safe to overwrite.
        if (kt + 2 < NK) {
            LOADSTAGE(kt + 2, (kt + 2) % 3);
        } else {
            asm volatile("cp.async.commit_group;" ::: "memory");
        }
        const float* As = sm + st * STAGEF;
        const float* Bs = As + 128 * GP;
#pragma unroll
        for (int ks = 0; ks < 4; ++ks) {
            wmma::fragment<wmma::matrix_a, 16, 16, 8, wmma::precision::tf32, wmma::row_major> a0, a1;
            wmma::load_matrix_sync(a0, As + (wy * 32) * GP + ks * 8, GP);
            wmma::load_matrix_sync(a1, As + (wy * 32 + 16) * GP + ks * 8, GP);
#pragma unroll
            for (int j = 0; j < 4; ++j) {
                wmma::fragment<wmma::matrix_b, 16, 16, 8, wmma::precision::tf32, wmma::col_major> bf;
                wmma::load_matrix_sync(bf, Bs + (wx * 64 + j * 16) * GP + ks * 8, GP);
                wmma::mma_sync(acc[0][j], a0, bf, acc[0][j]);
                wmma::mma_sync(acc[1][j], a1, bf, acc[1][j]);
            }
        }
    }
#undef LOADSTAGE

#pragma unroll
    for (int i = 0; i < 2; ++i)
#pragma unroll
        for (int j = 0; j < 4; ++j) {
            float* cp = g_C + (size_t)(mt * 128 + wy * 32 + i * 16) * NPAD
                        + nt * 128 + wx * 64 + j * 16;
            wmma::store_matrix_sync(cp, acc[i][j], NPAD, wmma::mem_row_major);
        }
}

// ---------------- kernel 5: persistent bidirectional LSTM scan ----------------
__device__ __forceinline__ float sigm(float x) {
    return 1.f / (1.f + __expf(-x));
}
__device__ __forceinline__ float tanh_fast(float x) {
    x = fminf(fmaxf(x, -15.f), 15.f);
    float e = __expf(-2.f * x);
    return (1.f - e) / (1.f + e);
}

extern __shared__ float sm_lstm[];
__global__ void __launch_bounds__(256, 1) k_lstm(
        const float* __restrict__ whf, const float* __restrict__ whb,
        const float* __restrict__ bihf, const float* __restrict__ bhhf,
        const float* __restrict__ bihb, const float* __restrict__ bhhb) {
    float* WhhS = sm_lstm;                   // [2][16][LDH]
    float* hS   = WhhS + 2 * 16 * LDH;       // [2][16][LDH]
    float* accS = hS + 2 * 16 * LDH;         // [8][16*LDA]
    float* cS   = accS + 8 * 16 * LDA;       // [2][64]
    float* bS   = cS + 128;                  // [2][16]

    int tid = threadIdx.x;
    int tile = blockIdx.x;                   // owns h-cols [4*tile, 4*tile+4)

    for (int e = tid; e < 2 * 16 * LDH; e += 256) {
        int k = e % LDH;
        int lrr = (e / LDH) & 15;
        int dir = e / (16 * LDH);
        int gate = lrr >> 2, cc = lrr & 3;
        int srow = gate * 300 + tile * 4 + cc;
        float v = 0.f;
        if (k < 300) v = wmma::__float_to_tf32((dir ? whb : whf)[srow * 300 + k]);
        WhhS[e] = v;
    }
    if (tid < 32) {
        int dir = tid >> 4, lrr = tid & 15;
        int gate = lrr >> 2, cc = lrr & 3;
        int srow = gate * 300 + tile * 4 + cc;
        bS[tid] = dir ? (bihb[srow] + bhhb[srow]) : (bihf[srow] + bhhf[srow]);
    }
    if (tid < 128) cS[tid] = 0.f;
    __syncthreads();

    int wid = tid >> 5;
    int dirw = wid >> 2, kq = wid & 3;       // warps 0-3 fwd, 4-7 bwd; k-split x4
    int edir = tid >> 6, eidx = tid & 63, ecc = eidx >> 4, eb = eidx & 15;

    // z double buffer: prefetch step 0
    float z0 = 0.f, z1 = 0.f, z2 = 0.f, z3 = 0.f;
    float n0 = 0.f, n1 = 0.f, n2 = 0.f, n3 = 0.f;
    if (tid < 128) {
        int pos0 = edir ? (Ss - 1) : 0;
        const float* crow = g_C + ((size_t)pos0 * Bb + eb) * NPAD
                            + (edir ? NDIRBASE : 0) + tile * 16;
        n0 = crow[0 + ecc]; n1 = crow[4 + ecc]; n2 = crow[8 + ecc]; n3 = crow[12 + ecc];
    }

    for (int g = 0; g < Tt * Ss; ++g) {
        int t = g / Ss, s = g % Ss;
        int parity = g & 1;
        z0 = n0; z1 = n1; z2 = n2; z3 = n3;

        // stage both directions' h into shared
        {
            const float4* hg = (const float4*)g_h;
            const int Q = LDK / 4;  // 80
            for (int i = tid; i < 2 * 16 * Q; i += 256) {
                int dr = i / (16 * Q);
                int rem = i % (16 * Q);
                int row = rem / Q, off = rem % Q;
                float4 v = hg[((dr * 2 + parity) * Bb + row) * Q + off];
                *(float4*)(hS + (dr * 16 + row) * LDH + off * 4) = v;
            }
        }
        __syncthreads();

        // prefetch next step's z
        if (tid < 128 && g + 1 < Tt * Ss) {
            int gn = g + 1;
            int tn = gn / Ss, sn = gn % Ss;
            int posn = edir ? (Ss - 1 - sn) : sn;
            const float* crow = g_C + ((size_t)(tn * Ss + posn) * Bb + eb) * NPAD
                                + (edir ? NDIRBASE : 0) + tile * 16;
            n0 = crow[0 + ecc]; n1 = crow[4 + ecc]; n2 = crow[8 + ecc]; n3 = crow[12 + ecc];
        }

        // recurrent matmul: [16b x 320k] x [320k x 16 gate-rows]
        {
            wmma::fragment<wmma::accumulator, 16, 16, 8, float> acc;
            wmma::fill_fragment(acc, 0.f);
#pragma unroll
            for (int itk = 0; itk < 10; ++itk) {
                int k = kq * 80 + itk * 8;
                wmma::fragment<wmma::matrix_a, 16, 16, 8, wmma::precision::tf32, wmma::row_major> af;
                wmma::fragment<wmma::matrix_b, 16, 16, 8, wmma::precision::tf32, wmma::col_major> bf;
                wmma::load_matrix_sync(af, hS + dirw * 16 * LDH + k, LDH);
                wmma::load_matrix_sync(bf, WhhS + dirw * 16 * LDH + k, LDH);
                wmma::mma_sync(acc, af, bf, acc);
            }
            wmma::store_matrix_sync(accS + wid * 16 * LDA, acc, LDA, wmma::mem_row_major);
        }
        __syncthreads();

        // gates + state update
        if (tid < 128) {
            int pos = edir ? (Ss - 1 - s) : s;
            float* ab = accS + edir * 4 * 16 * LDA + eb * LDA;
            const int W1 = 16 * LDA, W2 = 32 * LDA, W3 = 48 * LDA;
            float zi = z0 + bS[edir * 16 + 0 + ecc]  + ab[0 + ecc]  + ab[W1 + 0 + ecc]  + ab[W2 + 0 + ecc]  + ab[W3 + 0 + ecc];
            float zf = z1 + bS[edir * 16 + 4 + ecc]  + ab[4 + ecc]  + ab[W1 + 4 + ecc]  + ab[W2 + 4 + ecc]  + ab[W3 + 4 + ecc];
            float zg = z2 + bS[edir * 16 + 8 + ecc]  + ab[8 + ecc]  + ab[W1 + 8 + ecc]  + ab[W2 + 8 + ecc]  + ab[W3 + 8 + ecc];
            float zo = z3 + bS[edir * 16 + 12 + ecc] + ab[12 + ecc] + ab[W1 + 12 + ecc] + ab[W2 + 12 + ecc] + ab[W3 + 12 + ecc];
            float ig = sigm(zi);
            float fg = sigm(zf);
            float gg = tanh_fast(zg);
            float og = sigm(zo);
            float cold = cS[edir * 64 + eidx];
            float cnew = fg * cold + ig * gg;
            float hval = og * tanh_fast(cnew);
            cS[edir * 64 + eidx] = cnew;
            int jh = tile * 4 + ecc;
            g_h[((edir * 2 + (parity ^ 1)) * Bb + eb) * LDK + jh] = wmma::__float_to_tf32(hval);
            g_y[((size_t)(t * Ss + pos) * Bb + eb) * 600 + edir * 300 + jh] = hval;
        }
        __syncthreads();

        // grid barrier: per-CTA release slots + parallel acquire polling
        if (tid == 0) {
            __threadfence();
            asm volatile("st.global.release.gpu.u32 [%0], %1;"
                         :: "l"(g_slots + blockIdx.x * 8), "r"((unsigned)(g + 1)) : "memory");
        }
        if (tid < NCTA_L) {
            unsigned f;
            do {
                asm volatile("ld.global.acquire.gpu.u32 %0, [%1];"
                             : "=r"(f) : "l"(g_slots + tid * 8) : "memory");
            } while (f < (unsigned)(g + 1));
        }
        __syncthreads();
    }
}

// ---------------- kernel 6: classifier ----------------
__global__ void k_cls(const float* __restrict__ W, const float* __restrict__ bc,
                      float* __restrict__ out) {
    int t = blockIdx.x >> 4, b = blockIdx.x & 15;
    float a0 = 0.f, a1 = 0.f, a2 = 0.f, a3 = 0.f;
    const size_t NW = 120000;
    for (int idx = threadIdx.x; idx < (int)NW; idx += 256) {
        int s = idx / 600, c = idx % 600;
        float yv = g_y[((size_t)(t * Ss + s) * Bb + b) * 600 + c];
        yv = fmaxf(yv, 0.f);
        a0 += yv * W[idx];
        a1 += yv * W[NW + idx];
        a2 += yv * W[2 * NW + idx];
        a3 += yv * W[3 * NW + idx];
    }
#pragma unroll
    for (int off = 16; off; off >>= 1) {
        a0 += __shfl_down_sync(0xFFFFFFFFu, a0, off);
        a1 += __shfl_down_sync(0xFFFFFFFFu, a1, off);
        a2 += __shfl_down_sync(0xFFFFFFFFu, a2, off);
        a3 += __shfl_down_sync(0xFFFFFFFFu, a3, off);
    }
    __shared__ float rs[8][4];
    if ((threadIdx.x & 31) == 0) {
        int w = threadIdx.x >> 5;
        rs[w][0] = a0; rs[w][1] = a1; rs[w][2] = a2; rs[w][3] = a3;
    }
    __syncthreads();
    if (threadIdx.x < 4) {
        float sv = bc[threadIdx.x];
#pragma unroll
        for (int w = 0; w < 8; ++w) sv += rs[w][threadIdx.x];
        out[blockIdx.x * 4 + threadIdx.x] = sv;
    }
}

// ---------------- host launcher ----------------
extern "C" void kernel_launch(void* const* d_in, const int* in_sizes, int n_in,
                              void* d_out, int out_size) {
    const float* seq  = (const float*)d_in[1];
    const float* sp   = (const float*)d_in[2];
    const float* ep   = (const float*)d_in[3];
    const float* cp   = (const float*)d_in[4];
    const float* bsp  = (const float*)d_in[5];
    const float* bep  = (const float*)d_in[6];
    const float* bcp  = (const float*)d_in[7];
    const float* um   = (const float*)d_in[8];
    const float* nm   = (const float*)d_in[9];
    const float* am   = (const float*)d_in[10];
    const float* wihf = (const float*)d_in[11];
    const float* whhf = (const float*)d_in[12];
    const float* bihf = (const float*)d_in[13];
    const float* bhhf = (const float*)d_in[14];
    const float* wihb = (const float*)d_in[15];
    const float* whhb = (const float*)d_in[16];
    const float* bihb = (const float*)d_in[17];
    const float* bhhb = (const float*)d_in[18];
    const float* wcls = (const float*)d_in[19];
    const float* bcls = (const float*)d_in[20];
    float* out = (float*)d_out;

    const int LSTM_SMEM = (2 * 16 * LDH + 2 * 16 * LDH + 8 * 16 * LDA + 128 + 32) * 4;
    cudaFuncSetAttribute(k_lstm, cudaFuncAttributeMaxDynamicSharedMemorySize, LSTM_SMEM);
    cudaFuncSetAttribute(k_gemm2, cudaFuncAttributeMaxDynamicSharedMemorySize, GSMEM);

    void* slotsp = nullptr;
    void* hp = nullptr;
    cudaGetSymbolAddress(&slotsp, g_slots);
    cudaGetSymbolAddress(&hp, g_h);
    cudaMemsetAsync(slotsp, 0, sizeof(unsigned) * NCTA_L * 8);
    cudaMemsetAsync(hp, 0, sizeof(float) * 2 * 2 * Bb * LDK);

    k_weights<<<(Tt * Bb * Ss + 255) / 256, 256>>>(sp, ep, cp, bsp, bep, bcp, um, nm, am);
    k_wpad<<<NPAD, 256>>>(wihf, wihb);
    k_xbuild<<<Mm, 192>>>(seq);
    dim3 gg(NPAD / 128, Mm / 128);
    k_gemm2<<<gg, 256, GSMEM>>>();
    k_lstm<<<NCTA_L, 256, LSTM_SMEM>>>(whhf, whhb, bihf, bhhf, bihb, bhhb);
    k_cls<<<Tt * Bb, 256>>>(wcls, bcls, out);
}

// round 6
// speedup vs baseline: 2.1314x; 1.4989x over previous
#include <cuda_runtime.h>
#include <cuda_fp16.h>
#include <mma.h>
#include <cstdint>
#include <cstddef>

using namespace nvcuda;

#define Tt 10
#define Bb 16
#define Ss 200
#define Dd 768
#define K5 3840            // 5*D
#define NPAD 2432          // 1216 (fwd block) + 1216 (bwd block)
#define NDIRBASE 1216
#define Mm 32000           // T*S*B
#define LDK 320            // padded recurrent K in GLOBAL h buffer (halves)
#define LDH2 328           // padded shared stride (halves) for LSTM
#define LDA 20             // padded accS stride (floats)
#define NCTA_L 75

// ---------------- device scratch (allocation-free) ----------------
__device__ __half g_X[(size_t)Mm * K5];      // 245.8 MB fp16
__device__ __half g_W[(size_t)NPAD * K5];    // 18.7 MB fp16
__device__ float g_C[(size_t)Mm * NPAD];     // 311.3 MB
__device__ float g_ws[Tt * Bb * Ss];
__device__ float g_we[Tt * Bb * Ss];
__device__ float g_wbs[Bb * Ss];
__device__ float g_wbe[Bb * Ss];
__device__ float g_y[(size_t)Tt * Ss * Bb * 600];  // [t][s][b][2H]
__device__ __half g_h[2 * 2 * Bb * LDK];     // [dir][parity][b][LDK] fp16
__device__ unsigned g_slots[NCTA_L * 8];     // per-CTA barrier slots, 32B stride

// ---------------- helpers ----------------
__device__ __forceinline__ uint32_t smem_u32(const void* p) {
    uint32_t a;
    asm("{ .reg .u64 t; cvta.to.shared.u64 t, %1; cvt.u32.u64 %0, t; }" : "=r"(a) : "l"(p));
    return a;
}
__device__ __forceinline__ void cp16(uint32_t d, const void* s) {
    asm volatile("cp.async.cg.shared.global [%0], [%1], 16;" :: "r"(d), "l"(s) : "memory");
}

// ---------------- kernel 1: fused attention weights ----------------
__global__ void k_weights(const float* __restrict__ sp, const float* __restrict__ ep,
                          const float* __restrict__ cp,
                          const float* __restrict__ bsp, const float* __restrict__ bep,
                          const float* __restrict__ bcp,
                          const float* __restrict__ um, const float* __restrict__ nm,
                          const float* __restrict__ am) {
    int idx = blockIdx.x * blockDim.x + threadIdx.x;
    if (idx >= Tt * Bb * Ss) return;
    int t = idx / (Bb * Ss);
    int r = idx % (Bb * Ss);
    int b = r / Ss;
    int s = r % Ss;
    // masks are [B,T,S]
    float amv = am[(b * Tt + t) * Ss + s];
    float umv = um[(b * Tt + t) * Ss + s];
    float nmv = nm[(b * Tt + t) * Ss + s];
    const float* c = cp + (t * Bb + b) * 4;
    float wb = amv * c[0] + umv * c[1] + nmv * c[2];
    g_ws[idx] = sp[idx] * wb;
    g_we[idx] = ep[idx] * wb;
    if (t == 0) {
        const float* bc = bcp + b * 4;
        float wbb = amv * bc[0] + umv * bc[1] + nmv * bc[2];
        g_wbs[b * Ss + s] = bsp[b * Ss + s] * wbb;
        g_wbe[b * Ss + s] = bep[b * Ss + s] * wbb;
    }
}

// ---------------- kernel 2: stacked + gate-permuted fp16 Wih -----------------
__global__ void k_wpad(const float* __restrict__ wf, const float* __restrict__ wb) {
    int rrow = blockIdx.x;
    int dir = rrow >= NDIRBASE;
    int rp = dir ? rrow - NDIRBASE : rrow;
    const float* src = nullptr;
    if (rp < 1200) {
        int tile = rp >> 4, gate = (rp >> 2) & 3, cc = rp & 3;
        int srow = gate * 300 + tile * 4 + cc;
        src = (dir ? wb : wf) + (size_t)srow * K5;
    }
    __half* dst = g_W + (size_t)rrow * K5;
    for (int c = threadIdx.x * 4; c < K5; c += blockDim.x * 4) {
        float4 v = make_float4(0.f, 0.f, 0.f, 0.f);
        if (src) v = *(const float4*)(src + c);
        __half2 a = __floats2half2_rn(v.x, v.y);
        __half2 b2 = __floats2half2_rn(v.z, v.w);
        *(__half2*)(dst + c) = a;
        *(__half2*)(dst + c + 2) = b2;
    }
}

// ---------------- kernel 3: build X (fp16) ----------------
__global__ void k_xbuild(const float* __restrict__ seq) {
    int m = blockIdx.x;          // ((t*200+s)*16+b)
    int b = m & 15;
    int ts = m >> 4;
    int s = ts % Ss;
    int t = ts / Ss;
    int tp = (t > 0) ? (t - 1) : 0;
    int c = threadIdx.x * 4;     // 192 threads -> 768 cols
    const float4 sv = *(const float4*)(seq + (((size_t)(t * Bb + b) * Ss + s) * Dd) + c);
    const float4 pv = *(const float4*)(seq + (((size_t)(tp * Bb + b) * Ss + s) * Dd) + c);
    int widx = (t * Bb + b) * Ss + s;
    float w1 = g_ws[widx], w2 = g_we[widx];
    float wp1, wp2;
    if (t > 0) {
        int pidx = ((t - 1) * Bb + b) * Ss + s;
        wp1 = g_ws[pidx];
        wp2 = g_we[pidx];
    } else {
        wp1 = g_wbs[b * Ss + s];
        wp2 = g_wbe[b * Ss + s];
    }
    __half* X = g_X + (size_t)m * K5 + c;
#define R4(off, a, wgt) do { \
        __half2 _h0 = __floats2half2_rn((a).x * (wgt), (a).y * (wgt)); \
        __half2 _h1 = __floats2half2_rn((a).z * (wgt), (a).w * (wgt)); \
        *(__half2*)(X + (off)) = _h0; \
        *(__half2*)(X + (off) + 2) = _h1; } while (0)
    R4(0,    sv, 1.f);
    R4(768,  sv, w1);
    R4(1536, sv, w2);
    R4(2304, pv, wp1);
    R4(3072, pv, wp2);
#undef R4
}

// ---------------- kernel 4: pipelined fp16 wmma GEMM  C = X * W^T ------------
// CTA tile 128x128x32, 3-stage cp.async, stride 40 halves (80B rows).
#define GP2 40
#define STAGEH (2 * 128 * GP2)         // halves per stage (A + B)
#define GSMEM (3 * STAGEH * 2)         // 61440 B -> 2 CTAs/SM
#define NK (K5 / 32)                   // 120 k-tiles

__global__ void __launch_bounds__(256) k_gemm2() {
    extern __shared__ __half smh[];
    int tid = threadIdx.x;
    int mt = blockIdx.y, nt = blockIdx.x;
    uint32_t sbase = smem_u32(smh);

    int wid = tid >> 5;
    int wy = wid >> 1, wx = wid & 1;   // 4x2 warps; warp tile 32x64

    int lrow0 = tid >> 2;              // 64 rows per pass, 2 passes
    int lc4 = tid & 3;                 // 4 chunks of 8 halves per row

    const __half* AG = g_X + (size_t)(mt * 128) * K5;
    const __half* BG = g_W + (size_t)(nt * 128) * K5;

    wmma::fragment<wmma::accumulator, 16, 16, 16, float> acc[2][4];
#pragma unroll
    for (int i = 0; i < 2; ++i)
#pragma unroll
        for (int j = 0; j < 4; ++j) wmma::fill_fragment(acc[i][j], 0.f);

#define LOADSTAGE(kt, st) do { \
        uint32_t sa = sbase + (st) * STAGEH * 2; \
        uint32_t sbb = sa + 128 * GP2 * 2; \
        int kof = (kt) * 32 + lc4 * 8; \
        _Pragma("unroll") \
        for (int i = 0; i < 2; ++i) { \
            int row = lrow0 + i * 64; \
            cp16(sa  + (row * GP2 + lc4 * 8) * 2, AG + (size_t)row * K5 + kof); \
            cp16(sbb + (row * GP2 + lc4 * 8) * 2, BG + (size_t)row * K5 + kof); \
        } \
        asm volatile("cp.async.commit_group;" ::: "memory"); \
    } while (0)

    LOADSTAGE(0, 0);
    LOADSTAGE(1, 1);

    for (int kt = 0; kt < NK; ++kt) {
        int st = kt % 3;
        asm volatile("cp.async.wait_group 1;" ::: "memory");
        __syncthreads();
        if (kt + 2 < NK) {
            LOADSTAGE(kt + 2, (kt + 2) % 3);
        } else {
            asm volatile("cp.async.commit_group;" ::: "memory");
        }
        const __half* As = smh + st * STAGEH;
        const __half* Bs = As + 128 * GP2;
#pragma unroll
        for (int ks = 0; ks < 2; ++ks) {
            wmma::fragment<wmma::matrix_a, 16, 16, 16, half, wmma::row_major> a0, a1;
            wmma::load_matrix_sync(a0, As + (wy * 32) * GP2 + ks * 16, GP2);
            wmma::load_matrix_sync(a1, As + (wy * 32 + 16) * GP2 + ks * 16, GP2);
#pragma unroll
            for (int j = 0; j < 4; ++j) {
                wmma::fragment<wmma::matrix_b, 16, 16, 16, half, wmma::col_major> bf;
                wmma::load_matrix_sync(bf, Bs + (wx * 64 + j * 16) * GP2 + ks * 16, GP2);
                wmma::mma_sync(acc[0][j], a0, bf, acc[0][j]);
                wmma::mma_sync(acc[1][j], a1, bf, acc[1][j]);
            }
        }
    }
#undef LOADSTAGE

#pragma unroll
    for (int i = 0; i < 2; ++i)
#pragma unroll
        for (int j = 0; j < 4; ++j) {
            float* cp = g_C + (size_t)(mt * 128 + wy * 32 + i * 16) * NPAD
                        + nt * 128 + wx * 64 + j * 16;
            wmma::store_matrix_sync(cp, acc[i][j], NPAD, wmma::mem_row_major);
        }
}

// ---------------- kernel 5: persistent bidirectional LSTM scan (fp16 mma) ----
__device__ __forceinline__ float sigm(float x) {
    return 1.f / (1.f + __expf(-x));
}
__device__ __forceinline__ float tanh_fast(float x) {
    x = fminf(fmaxf(x, -15.f), 15.f);
    float e = __expf(-2.f * x);
    return (1.f - e) / (1.f + e);
}

extern __shared__ __half sm_lstm[];
__global__ void __launch_bounds__(256, 1) k_lstm(
        const float* __restrict__ whf, const float* __restrict__ whb,
        const float* __restrict__ bihf, const float* __restrict__ bhhf,
        const float* __restrict__ bihb, const float* __restrict__ bhhb) {
    __half* WhhS = sm_lstm;                      // [2][16][LDH2] halves
    __half* hS   = WhhS + 2 * 16 * LDH2;         // [2][16][LDH2] halves
    float* accS  = (float*)(hS + 2 * 16 * LDH2); // [8][16*LDA]
    float* cS    = accS + 8 * 16 * LDA;          // [2][64]
    float* bS    = cS + 128;                     // [2][16]

    int tid = threadIdx.x;
    int tile = blockIdx.x;                       // owns h-cols [4*tile, 4*tile+4)

    // prologue: Whh slices (gate-permuted, fp16) resident in shared
    for (int e = tid; e < 2 * 16 * LDH2; e += 256) {
        int k = e % LDH2;
        int lrr = (e / LDH2) & 15;
        int dir = e / (16 * LDH2);
        int gate = lrr >> 2, cc = lrr & 3;
        int srow = gate * 300 + tile * 4 + cc;
        float v = 0.f;
        if (k < 300) v = (dir ? whb : whf)[srow * 300 + k];
        WhhS[e] = __float2half(v);
    }
    if (tid < 32) {
        int dir = tid >> 4, lrr = tid & 15;
        int gate = lrr >> 2, cc = lrr & 3;
        int srow = gate * 300 + tile * 4 + cc;
        bS[tid] = dir ? (bihb[srow] + bhhb[srow]) : (bihf[srow] + bhhf[srow]);
    }
    if (tid < 128) cS[tid] = 0.f;
    __syncthreads();

    int wid = tid >> 5;
    int dirw = wid >> 2, kq = wid & 3;       // warps 0-3 fwd, 4-7 bwd; k-split x4
    int edir = tid >> 6, eidx = tid & 63, ecc = eidx >> 4, eb = eidx & 15;

    // z double buffer: prefetch step 0
    float z0 = 0.f, z1 = 0.f, z2 = 0.f, z3 = 0.f;
    float n0 = 0.f, n1 = 0.f, n2 = 0.f, n3 = 0.f;
    if (tid < 128) {
        int pos0 = edir ? (Ss - 1) : 0;
        const float* crow = g_C + ((size_t)pos0 * Bb + eb) * NPAD
                            + (edir ? NDIRBASE : 0) + tile * 16;
        n0 = crow[0 + ecc]; n1 = crow[4 + ecc]; n2 = crow[8 + ecc]; n3 = crow[12 + ecc];
    }

    for (int g = 0; g < Tt * Ss; ++g) {
        int t = g / Ss, s = g % Ss;
        int parity = g & 1;
        z0 = n0; z1 = n1; z2 = n2; z3 = n3;

        // stage both directions' h into shared (fp16, 20KB total)
        {
            const uint4* hg = (const uint4*)g_h;      // 8 halves per uint4
            const int Q = LDK / 8;                    // 40 uint4 per row
            for (int i = tid; i < 2 * 16 * Q; i += 256) {
                int dr = i / (16 * Q);
                int rem = i % (16 * Q);
                int row = rem / Q, off = rem % Q;
                uint4 v = hg[((dr * 2 + parity) * Bb + row) * Q + off];
                *(uint4*)(hS + (dr * 16 + row) * LDH2 + off * 8) = v;
            }
        }
        __syncthreads();

        // prefetch next step's z
        if (tid < 128 && g + 1 < Tt * Ss) {
            int gn = g + 1;
            int tn = gn / Ss, sn = gn % Ss;
            int posn = edir ? (Ss - 1 - sn) : sn;
            const float* crow = g_C + ((size_t)(tn * Ss + posn) * Bb + eb) * NPAD
                                + (edir ? NDIRBASE : 0) + tile * 16;
            n0 = crow[0 + ecc]; n1 = crow[4 + ecc]; n2 = crow[8 + ecc]; n3 = crow[12 + ecc];
        }

        // recurrent matmul: [16b x 320k] x [320k x 16 gate-rows], fp16 k16
        {
            wmma::fragment<wmma::accumulator, 16, 16, 16, float> acc;
            wmma::fill_fragment(acc, 0.f);
#pragma unroll
            for (int itk = 0; itk < 5; ++itk) {
                int k = kq * 80 + itk * 16;
                wmma::fragment<wmma::matrix_a, 16, 16, 16, half, wmma::row_major> af;
                wmma::fragment<wmma::matrix_b, 16, 16, 16, half, wmma::col_major> bf;
                wmma::load_matrix_sync(af, hS + dirw * 16 * LDH2 + k, LDH2);
                wmma::load_matrix_sync(bf, WhhS + dirw * 16 * LDH2 + k, LDH2);
                wmma::mma_sync(acc, af, bf, acc);
            }
            wmma::store_matrix_sync(accS + wid * 16 * LDA, acc, LDA, wmma::mem_row_major);
        }
        __syncthreads();

        // gates + state update
        if (tid < 128) {
            int pos = edir ? (Ss - 1 - s) : s;
            float* ab = accS + edir * 4 * 16 * LDA + eb * LDA;
            const int W1 = 16 * LDA, W2 = 32 * LDA, W3 = 48 * LDA;
            float zi = z0 + bS[edir * 16 + 0 + ecc]  + ab[0 + ecc]  + ab[W1 + 0 + ecc]  + ab[W2 + 0 + ecc]  + ab[W3 + 0 + ecc];
            float zf = z1 + bS[edir * 16 + 4 + ecc]  + ab[4 + ecc]  + ab[W1 + 4 + ecc]  + ab[W2 + 4 + ecc]  + ab[W3 + 4 + ecc];
            float zg = z2 + bS[edir * 16 + 8 + ecc]  + ab[8 + ecc]  + ab[W1 + 8 + ecc]  + ab[W2 + 8 + ecc]  + ab[W3 + 8 + ecc];
            float zo = z3 + bS[edir * 16 + 12 + ecc] + ab[12 + ecc] + ab[W1 + 12 + ecc] + ab[W2 + 12 + ecc] + ab[W3 + 12 + ecc];
            float ig = sigm(zi);
            float fg = sigm(zf);
            float gg = tanh_fast(zg);
            float og = sigm(zo);
            float cold = cS[edir * 64 + eidx];
            float cnew = fg * cold + ig * gg;
            float hval = og * tanh_fast(cnew);
            cS[edir * 64 + eidx] = cnew;
            int jh = tile * 4 + ecc;
            g_h[((edir * 2 + (parity ^ 1)) * Bb + eb) * LDK + jh] = __float2half(hval);
            g_y[((size_t)(t * Ss + pos) * Bb + eb) * 600 + edir * 300 + jh] = hval;
        }
        __syncthreads();

        // grid barrier: per-CTA release slots + parallel acquire polling
        if (tid == 0) {
            __threadfence();
            asm volatile("st.global.release.gpu.u32 [%0], %1;"
                         :: "l"(g_slots + blockIdx.x * 8), "r"((unsigned)(g + 1)) : "memory");
        }
        if (tid < NCTA_L) {
            unsigned f;
            do {
                asm volatile("ld.global.acquire.gpu.u32 %0, [%1];"
                             : "=r"(f) : "l"(g_slots + tid * 8) : "memory");
            } while (f < (unsigned)(g + 1));
        }
        __syncthreads();
    }
}

// ---------------- kernel 6: classifier ----------------
__global__ void k_cls(const float* __restrict__ W, const float* __restrict__ bc,
                      float* __restrict__ out) {
    int t = blockIdx.x >> 4, b = blockIdx.x & 15;
    float a0 = 0.f, a1 = 0.f, a2 = 0.f, a3 = 0.f;
    const size_t NW = 120000;
    for (int idx = threadIdx.x; idx < (int)NW; idx += 256) {
        int s = idx / 600, c = idx % 600;
        float yv = g_y[((size_t)(t * Ss + s) * Bb + b) * 600 + c];
        yv = fmaxf(yv, 0.f);
        a0 += yv * W[idx];
        a1 += yv * W[NW + idx];
        a2 += yv * W[2 * NW + idx];
        a3 += yv * W[3 * NW + idx];
    }
#pragma unroll
    for (int off = 16; off; off >>= 1) {
        a0 += __shfl_down_sync(0xFFFFFFFFu, a0, off);
        a1 += __shfl_down_sync(0xFFFFFFFFu, a1, off);
        a2 += __shfl_down_sync(0xFFFFFFFFu, a2, off);
        a3 += __shfl_down_sync(0xFFFFFFFFu, a3, off);
    }
    __shared__ float rs[8][4];
    if ((threadIdx.x & 31) == 0) {
        int w = threadIdx.x >> 5;
        rs[w][0] = a0; rs[w][1] = a1; rs[w][2] = a2; rs[w][3] = a3;
    }
    __syncthreads();
    if (threadIdx.x < 4) {
        float sv = bc[threadIdx.x];
#pragma unroll
        for (int w = 0; w < 8; ++w) sv += rs[w][threadIdx.x];
        out[blockIdx.x * 4 + threadIdx.x] = sv;
    }
}

// ---------------- host launcher ----------------
extern "C" void kernel_launch(void* const* d_in, const int* in_sizes, int n_in,
                              void* d_out, int out_size) {
    const float* seq  = (const float*)d_in[1];
    const float* sp   = (const float*)d_in[2];
    const float* ep   = (const float*)d_in[3];
    const float* cp   = (const float*)d_in[4];
    const float* bsp  = (const float*)d_in[5];
    const float* bep  = (const float*)d_in[6];
    const float* bcp  = (const float*)d_in[7];
    const float* um   = (const float*)d_in[8];
    const float* nm   = (const float*)d_in[9];
    const float* am   = (const float*)d_in[10];
    const float* wihf = (const float*)d_in[11];
    const float* whhf = (const float*)d_in[12];
    const float* bihf = (const float*)d_in[13];
    const float* bhhf = (const float*)d_in[14];
    const float* wihb = (const float*)d_in[15];
    const float* whhb = (const float*)d_in[16];
    const float* bihb = (const float*)d_in[17];
    const float* bhhb = (const float*)d_in[18];
    const float* wcls = (const float*)d_in[19];
    const float* bcls = (const float*)d_in[20];
    float* out = (float*)d_out;

    const int LSTM_SMEM = (2 * 16 * LDH2) * 2 * 2            // WhhS + hS halves
                        + (8 * 16 * LDA + 128 + 32) * 4;     // accS + cS + bS
    cudaFuncSetAttribute(k_lstm, cudaFuncAttributeMaxDynamicSharedMemorySize, LSTM_SMEM);
    cudaFuncSetAttribute(k_gemm2, cudaFuncAttributeMaxDynamicSharedMemorySize, GSMEM);

    void* slotsp = nullptr;
    void* hp = nullptr;
    cudaGetSymbolAddress(&slotsp, g_slots);
    cudaGetSymbolAddress(&hp, g_h);
    cudaMemsetAsync(slotsp, 0, sizeof(unsigned) * NCTA_L * 8);
    cudaMemsetAsync(hp, 0, sizeof(__half) * 2 * 2 * Bb * LDK);

    k_weights<<<(Tt * Bb * Ss + 255) / 256, 256>>>(sp, ep, cp, bsp, bep, bcp, um, nm, am);
    k_wpad<<<NPAD, 256>>>(wihf, wihb);
    k_xbuild<<<Mm, 192>>>(seq);
    dim3 gg(NPAD / 128, Mm / 128);
    k_gemm2<<<gg, 256, GSMEM>>>();
    k_lstm<<<NCTA_L, 256, LSTM_SMEM>>>(whhf, whhb, bihf, bhhf, bihb, bhhb);
    k_cls<<<Tt * Bb, 256>>>(wcls, bcls, out);
}

// round 7
// speedup vs baseline: 2.6512x; 1.2439x over previous
#include <cuda_runtime.h>
#include <cuda_fp16.h>
#include <mma.h>
#include <cstdint>
#include <cstddef>

using namespace nvcuda;

#define Tt 10
#define Bb 16
#define Ss 200
#define Dd 768
#define K5 3840            // 5*D
#define NPAD 2432          // 1216 (fwd block) + 1216 (bwd block)
#define NDIRBASE 1216
#define Mm 32000           // T*S*B
#define LDK 320            // padded recurrent K in GLOBAL h buffer (halves)
#define LDW 344            // Whh staging stride (halves); 172 words mod 32 = 12
#define LDA 20             // padded accS stride (floats)
#define NCTA_L 75

// ---------------- device scratch (allocation-free) ----------------
__device__ __half g_X[(size_t)Mm * K5];      // 245.8 MB fp16
__device__ __half g_W[(size_t)NPAD * K5];    // 18.7 MB fp16
__device__ float g_C[(size_t)Mm * NPAD];     // 311.3 MB
__device__ float g_ws[Tt * Bb * Ss];
__device__ float g_we[Tt * Bb * Ss];
__device__ float g_wbs[Bb * Ss];
__device__ float g_wbe[Bb * Ss];
__device__ float g_y[(size_t)Tt * Ss * Bb * 600];  // [t][s][b][2H]
__device__ __half g_h[2 * 2 * Bb * LDK];     // [dir][parity][b][LDK] fp16
__device__ unsigned g_slots[NCTA_L * 8];     // per-CTA barrier slots, 32B stride

// ---------------- helpers ----------------
__device__ __forceinline__ uint32_t smem_u32(const void* p) {
    uint32_t a;
    asm("{ .reg .u64 t; cvta.to.shared.u64 t, %1; cvt.u32.u64 %0, t; }" : "=r"(a) : "l"(p));
    return a;
}
__device__ __forceinline__ void cp16(uint32_t d, const void* s) {
    asm volatile("cp.async.cg.shared.global [%0], [%1], 16;" :: "r"(d), "l"(s) : "memory");
}

// ---------------- kernel 1: fused attention weights ----------------
__global__ void k_weights(const float* __restrict__ sp, const float* __restrict__ ep,
                          const float* __restrict__ cp,
                          const float* __restrict__ bsp, const float* __restrict__ bep,
                          const float* __restrict__ bcp,
                          const float* __restrict__ um, const float* __restrict__ nm,
                          const float* __restrict__ am) {
    int idx = blockIdx.x * blockDim.x + threadIdx.x;
    if (idx >= Tt * Bb * Ss) return;
    int t = idx / (Bb * Ss);
    int r = idx % (Bb * Ss);
    int b = r / Ss;
    int s = r % Ss;
    // masks are [B,T,S]
    float amv = am[(b * Tt + t) * Ss + s];
    float umv = um[(b * Tt + t) * Ss + s];
    float nmv = nm[(b * Tt + t) * Ss + s];
    const float* c = cp + (t * Bb + b) * 4;
    float wb = amv * c[0] + umv * c[1] + nmv * c[2];
    g_ws[idx] = sp[idx] * wb;
    g_we[idx] = ep[idx] * wb;
    if (t == 0) {
        const float* bc = bcp + b * 4;
        float wbb = amv * bc[0] + umv * bc[1] + nmv * bc[2];
        g_wbs[b * Ss + s] = bsp[b * Ss + s] * wbb;
        g_wbe[b * Ss + s] = bep[b * Ss + s] * wbb;
    }
}

// ---------------- kernel 2: stacked + gate-permuted fp16 Wih -----------------
__global__ void k_wpad(const float* __restrict__ wf, const float* __restrict__ wb) {
    int rrow = blockIdx.x;
    int dir = rrow >= NDIRBASE;
    int rp = dir ? rrow - NDIRBASE : rrow;
    const float* src = nullptr;
    if (rp < 1200) {
        int tile = rp >> 4, gate = (rp >> 2) & 3, cc = rp & 3;
        int srow = gate * 300 + tile * 4 + cc;
        src = (dir ? wb : wf) + (size_t)srow * K5;
    }
    __half* dst = g_W + (size_t)rrow * K5;
    for (int c = threadIdx.x * 4; c < K5; c += blockDim.x * 4) {
        float4 v = make_float4(0.f, 0.f, 0.f, 0.f);
        if (src) v = *(const float4*)(src + c);
        __half2 a = __floats2half2_rn(v.x, v.y);
        __half2 b2 = __floats2half2_rn(v.z, v.w);
        *(__half2*)(dst + c) = a;
        *(__half2*)(dst + c + 2) = b2;
    }
}

// ---------------- kernel 3: build X (fp16) ----------------
__global__ void k_xbuild(const float* __restrict__ seq) {
    int m = blockIdx.x;          // ((t*200+s)*16+b)
    int b = m & 15;
    int ts = m >> 4;
    int s = ts % Ss;
    int t = ts / Ss;
    int tp = (t > 0) ? (t - 1) : 0;
    int c = threadIdx.x * 4;     // 192 threads -> 768 cols
    const float4 sv = *(const float4*)(seq + (((size_t)(t * Bb + b) * Ss + s) * Dd) + c);
    const float4 pv = *(const float4*)(seq + (((size_t)(tp * Bb + b) * Ss + s) * Dd) + c);
    int widx = (t * Bb + b) * Ss + s;
    float w1 = g_ws[widx], w2 = g_we[widx];
    float wp1, wp2;
    if (t > 0) {
        int pidx = ((t - 1) * Bb + b) * Ss + s;
        wp1 = g_ws[pidx];
        wp2 = g_we[pidx];
    } else {
        wp1 = g_wbs[b * Ss + s];
        wp2 = g_wbe[b * Ss + s];
    }
    __half* X = g_X + (size_t)m * K5 + c;
#define R4(off, a, wgt) do { \
        __half2 _h0 = __floats2half2_rn((a).x * (wgt), (a).y * (wgt)); \
        __half2 _h1 = __floats2half2_rn((a).z * (wgt), (a).w * (wgt)); \
        *(__half2*)(X + (off)) = _h0; \
        *(__half2*)(X + (off) + 2) = _h1; } while (0)
    R4(0,    sv, 1.f);
    R4(768,  sv, w1);
    R4(1536, sv, w2);
    R4(2304, pv, wp1);
    R4(3072, pv, wp2);
#undef R4
}

// ---------------- kernel 4: pipelined fp16 wmma GEMM  C = X * W^T ------------
#define GP2 40
#define STAGEH (2 * 128 * GP2)         // halves per stage (A + B)
#define GSMEM (3 * STAGEH * 2)         // 61440 B -> 2 CTAs/SM
#define NK (K5 / 32)                   // 120 k-tiles

__global__ void __launch_bounds__(256) k_gemm2() {
    extern __shared__ __half smh[];
    int tid = threadIdx.x;
    int mt = blockIdx.y, nt = blockIdx.x;
    uint32_t sbase = smem_u32(smh);

    int wid = tid >> 5;
    int wy = wid >> 1, wx = wid & 1;   // 4x2 warps; warp tile 32x64

    int lrow0 = tid >> 2;              // 64 rows per pass, 2 passes
    int lc4 = tid & 3;                 // 4 chunks of 8 halves per row

    const __half* AG = g_X + (size_t)(mt * 128) * K5;
    const __half* BG = g_W + (size_t)(nt * 128) * K5;

    wmma::fragment<wmma::accumulator, 16, 16, 16, float> acc[2][4];
#pragma unroll
    for (int i = 0; i < 2; ++i)
#pragma unroll
        for (int j = 0; j < 4; ++j) wmma::fill_fragment(acc[i][j], 0.f);

#define LOADSTAGE(kt, st) do { \
        uint32_t sa = sbase + (st) * STAGEH * 2; \
        uint32_t sbb = sa + 128 * GP2 * 2; \
        int kof = (kt) * 32 + lc4 * 8; \
        _Pragma("unroll") \
        for (int i = 0; i < 2; ++i) { \
            int row = lrow0 + i * 64; \
            cp16(sa  + (row * GP2 + lc4 * 8) * 2, AG + (size_t)row * K5 + kof); \
            cp16(sbb + (row * GP2 + lc4 * 8) * 2, BG + (size_t)row * K5 + kof); \
        } \
        asm volatile("cp.async.commit_group;" ::: "memory"); \
    } while (0)

    LOADSTAGE(0, 0);
    LOADSTAGE(1, 1);

    for (int kt = 0; kt < NK; ++kt) {
        int st = kt % 3;
        asm volatile("cp.async.wait_group 1;" ::: "memory");
        __syncthreads();
        if (kt + 2 < NK) {
            LOADSTAGE(kt + 2, (kt + 2) % 3);
        } else {
            asm volatile("cp.async.commit_group;" ::: "memory");
        }
        const __half* As = smh + st * STAGEH;
        const __half* Bs = As + 128 * GP2;
#pragma unroll
        for (int ks = 0; ks < 2; ++ks) {
            wmma::fragment<wmma::matrix_a, 16, 16, 16, half, wmma::row_major> a0, a1;
            wmma::load_matrix_sync(a0, As + (wy * 32) * GP2 + ks * 16, GP2);
            wmma::load_matrix_sync(a1, As + (wy * 32 + 16) * GP2 + ks * 16, GP2);
#pragma unroll
            for (int j = 0; j < 4; ++j) {
                wmma::fragment<wmma::matrix_b, 16, 16, 16, half, wmma::col_major> bf;
                wmma::load_matrix_sync(bf, Bs + (wx * 64 + j * 16) * GP2 + ks * 16, GP2);
                wmma::mma_sync(acc[0][j], a0, bf, acc[0][j]);
                wmma::mma_sync(acc[1][j], a1, bf, acc[1][j]);
            }
        }
    }
#undef LOADSTAGE

#pragma unroll
    for (int i = 0; i < 2; ++i)
#pragma unroll
        for (int j = 0; j < 4; ++j) {
            float* cp = g_C + (size_t)(mt * 128 + wy * 32 + i * 16) * NPAD
                        + nt * 128 + wx * 64 + j * 16;
            wmma::store_matrix_sync(cp, acc[i][j], NPAD, wmma::mem_row_major);
        }
}

// ---------------- kernel 5: persistent bidirectional LSTM scan ----------------
// Whh fragments register-resident; A fragments loaded straight from L2 (g_h).
__device__ __forceinline__ float sigm(float x) {
    return 1.f / (1.f + __expf(-x));
}
__device__ __forceinline__ float tanh_fast(float x) {
    x = fminf(fmaxf(x, -15.f), 15.f);
    float e = __expf(-2.f * x);
    return (1.f - e) / (1.f + e);
}

__global__ void __launch_bounds__(256, 1) k_lstm(
        const float* __restrict__ whf, const float* __restrict__ whb,
        const float* __restrict__ bihf, const float* __restrict__ bhhf,
        const float* __restrict__ bihb, const float* __restrict__ bhhb) {
    __shared__ __half WhhS[2 * 16 * LDW];    // prologue staging only
    __shared__ float accS[8 * 16 * LDA];
    __shared__ float cS[128];
    __shared__ float bS[32];

    int tid = threadIdx.x;
    int tile = blockIdx.x;                   // owns h-cols [4*tile, 4*tile+4)

    // prologue: stage Whh slices (gate-permuted, fp16) into shared
    for (int e = tid; e < 2 * 16 * LDW; e += 256) {
        int k = e % LDW;
        int lrr = (e / LDW) & 15;
        int dir = e / (16 * LDW);
        int gate = lrr >> 2, cc = lrr & 3;
        int srow = gate * 300 + tile * 4 + cc;
        float v = 0.f;
        if (k < 300) v = (dir ? whb : whf)[srow * 300 + k];
        WhhS[e] = __float2half(v);
    }
    if (tid < 32) {
        int dir = tid >> 4, lrr = tid & 15;
        int gate = lrr >> 2, cc = lrr & 3;
        int srow = gate * 300 + tile * 4 + cc;
        bS[tid] = dir ? (bihb[srow] + bhhb[srow]) : (bihf[srow] + bhhf[srow]);
    }
    if (tid < 128) cS[tid] = 0.f;
    __syncthreads();

    int wid = tid >> 5;
    int dirw = wid >> 2, kq = wid & 3;       // warps 0-3 fwd, 4-7 bwd; k-split x4
    int edir = tid >> 6, eidx = tid & 63, ecc = eidx >> 4, eb = eidx & 15;

    // register-resident B fragments: constant across all 2000 steps
    wmma::fragment<wmma::matrix_b, 16, 16, 16, half, wmma::col_major> Bf[5];
#pragma unroll
    for (int itk = 0; itk < 5; ++itk)
        wmma::load_matrix_sync(Bf[itk], WhhS + dirw * 16 * LDW + kq * 80 + itk * 16, LDW);
    __syncthreads();

    // z double buffer: prefetch step 0
    float z0 = 0.f, z1 = 0.f, z2 = 0.f, z3 = 0.f;
    float n0 = 0.f, n1 = 0.f, n2 = 0.f, n3 = 0.f;
    if (tid < 128) {
        int pos0 = edir ? (Ss - 1) : 0;
        const float* crow = g_C + ((size_t)pos0 * Bb + eb) * NPAD
                            + (edir ? NDIRBASE : 0) + tile * 16;
        n0 = crow[0 + ecc]; n1 = crow[4 + ecc]; n2 = crow[8 + ecc]; n3 = crow[12 + ecc];
    }

    for (int g = 0; g < Tt * Ss; ++g) {
        int t = g / Ss, s = g % Ss;
        int parity = g & 1;
        z0 = n0; z1 = n1; z2 = n2; z3 = n3;

        // recurrent matmul: A fragments straight from global (L2), B from regs
        {
            wmma::fragment<wmma::accumulator, 16, 16, 16, float> acc;
            wmma::fill_fragment(acc, 0.f);
            const __half* hbase = g_h + ((size_t)(dirw * 2 + parity) * Bb) * LDK + kq * 80;
#pragma unroll
            for (int itk = 0; itk < 5; ++itk) {
                wmma::fragment<wmma::matrix_a, 16, 16, 16, half, wmma::row_major> af;
                wmma::load_matrix_sync(af, hbase + itk * 16, LDK);
                wmma::mma_sync(acc, af, Bf[itk], acc);
            }
            wmma::store_matrix_sync(accS + wid * 16 * LDA, acc, LDA, wmma::mem_row_major);
        }

        // prefetch next step's z while acc settles
        if (tid < 128 && g + 1 < Tt * Ss) {
            int gn = g + 1;
            int tn = gn / Ss, sn = gn % Ss;
            int posn = edir ? (Ss - 1 - sn) : sn;
            const float* crow = g_C + ((size_t)(tn * Ss + posn) * Bb + eb) * NPAD
                                + (edir ? NDIRBASE : 0) + tile * 16;
            n0 = crow[0 + ecc]; n1 = crow[4 + ecc]; n2 = crow[8 + ecc]; n3 = crow[12 + ecc];
        }
        __syncthreads();

        // gates + state update
        if (tid < 128) {
            int pos = edir ? (Ss - 1 - s) : s;
            float* ab = accS + edir * 4 * 16 * LDA + eb * LDA;
            const int W1 = 16 * LDA, W2 = 32 * LDA, W3 = 48 * LDA;
            float zi = z0 + bS[edir * 16 + 0 + ecc]  + ab[0 + ecc]  + ab[W1 + 0 + ecc]  + ab[W2 + 0 + ecc]  + ab[W3 + 0 + ecc];
            float zf = z1 + bS[edir * 16 + 4 + ecc]  + ab[4 + ecc]  + ab[W1 + 4 + ecc]  + ab[W2 + 4 + ecc]  + ab[W3 + 4 + ecc];
            float zg = z2 + bS[edir * 16 + 8 + ecc]  + ab[8 + ecc]  + ab[W1 + 8 + ecc]  + ab[W2 + 8 + ecc]  + ab[W3 + 8 + ecc];
            float zo = z3 + bS[edir * 16 + 12 + ecc] + ab[12 + ecc] + ab[W1 + 12 + ecc] + ab[W2 + 12 + ecc] + ab[W3 + 12 + ecc];
            float ig = sigm(zi);
            float fg = sigm(zf);
            float gg = tanh_fast(zg);
            float og = sigm(zo);
            float cold = cS[edir * 64 + eidx];
            float cnew = fg * cold + ig * gg;
            float hval = og * tanh_fast(cnew);
            cS[edir * 64 + eidx] = cnew;
            int jh = tile * 4 + ecc;
            g_h[((edir * 2 + (parity ^ 1)) * Bb + eb) * LDK + jh] = __float2half(hval);
            g_y[((size_t)(t * Ss + pos) * Bb + eb) * 600 + edir * 300 + jh] = hval;
        }
        __syncthreads();

        // grid barrier: per-CTA release slots + parallel acquire polling
        // (release after __syncthreads is cumulative: publishes all CTA stores)
        if (tid == 0) {
            asm volatile("st.global.release.gpu.u32 [%0], %1;"
                         :: "l"(g_slots + blockIdx.x * 8), "r"((unsigned)(g + 1)) : "memory");
        }
        if (tid < NCTA_L) {
            unsigned f;
            do {
                asm volatile("ld.global.acquire.gpu.u32 %0, [%1];"
                             : "=r"(f) : "l"(g_slots + tid * 8) : "memory");
            } while (f < (unsigned)(g + 1));
        }
        __syncthreads();
    }
}

// ---------------- kernel 6: classifier ----------------
__global__ void k_cls(const float* __restrict__ W, const float* __restrict__ bc,
                      float* __restrict__ out) {
    int t = blockIdx.x >> 4, b = blockIdx.x & 15;
    float a0 = 0.f, a1 = 0.f, a2 = 0.f, a3 = 0.f;
    const size_t NW = 120000;
    for (int idx = threadIdx.x; idx < (int)NW; idx += 256) {
        int s = idx / 600, c = idx % 600;
        float yv = g_y[((size_t)(t * Ss + s) * Bb + b) * 600 + c];
        yv = fmaxf(yv, 0.f);
        a0 += yv * W[idx];
        a1 += yv * W[NW + idx];
        a2 += yv * W[2 * NW + idx];
        a3 += yv * W[3 * NW + idx];
    }
#pragma unroll
    for (int off = 16; off; off >>= 1) {
        a0 += __shfl_down_sync(0xFFFFFFFFu, a0, off);
        a1 += __shfl_down_sync(0xFFFFFFFFu, a1, off);
        a2 += __shfl_down_sync(0xFFFFFFFFu, a2, off);
        a3 += __shfl_down_sync(0xFFFFFFFFu, a3, off);
    }
    __shared__ float rs[8][4];
    if ((threadIdx.x & 31) == 0) {
        int w = threadIdx.x >> 5;
        rs[w][0] = a0; rs[w][1] = a1; rs[w][2] = a2; rs[w][3] = a3;
    }
    __syncthreads();
    if (threadIdx.x < 4) {
        float sv = bc[threadIdx.x];
#pragma unroll
        for (int w = 0; w < 8; ++w) sv += rs[w][threadIdx.x];
        out[blockIdx.x * 4 + threadIdx.x] = sv;
    }
}

// ---------------- host launcher ----------------
extern "C" void kernel_launch(void* const* d_in, const int* in_sizes, int n_in,
                              void* d_out, int out_size) {
    const float* seq  = (const float*)d_in[1];
    const float* sp   = (const float*)d_in[2];
    const float* ep   = (const float*)d_in[3];
    const float* cp   = (const float*)d_in[4];
    const float* bsp  = (const float*)d_in[5];
    const float* bep  = (const float*)d_in[6];
    const float* bcp  = (const float*)d_in[7];
    const float* um   = (const float*)d_in[8];
    const float* nm   = (const float*)d_in[9];
    const float* am   = (const float*)d_in[10];
    const float* wihf = (const float*)d_in[11];
    const float* whhf = (const float*)d_in[12];
    const float* bihf = (const float*)d_in[13];
    const float* bhhf = (const float*)d_in[14];
    const float* wihb = (const float*)d_in[15];
    const float* whhb = (const float*)d_in[16];
    const float* bihb = (const float*)d_in[17];
    const float* bhhb = (const float*)d_in[18];
    const float* wcls = (const float*)d_in[19];
    const float* bcls = (const float*)d_in[20];
    float* out = (float*)d_out;

    cudaFuncSetAttribute(k_gemm2, cudaFuncAttributeMaxDynamicSharedMemorySize, GSMEM);

    void* slotsp = nullptr;
    void* hp = nullptr;
    cudaGetSymbolAddress(&slotsp, g_slots);
    cudaGetSymbolAddress(&hp, g_h);
    cudaMemsetAsync(slotsp, 0, sizeof(unsigned) * NCTA_L * 8);
    cudaMemsetAsync(hp, 0, sizeof(__half) * 2 * 2 * Bb * LDK);

    k_weights<<<(Tt * Bb * Ss + 255) / 256, 256>>>(sp, ep, cp, bsp, bep, bcp, um, nm, am);
    k_wpad<<<NPAD, 256>>>(wihf, wihb);
    k_xbuild<<<Mm, 192>>>(seq);
    dim3 gg(NPAD / 128, Mm / 128);
    k_gemm2<<<gg, 256, GSMEM>>>();
    k_lstm<<<NCTA_L, 256>>>(whhf, whhb, bihf, bhhf, bihb, bhhb);
    k_cls<<<Tt * Bb, 256>>>(wcls, bcls, out);
}